// round 12
// baseline (speedup 1.0000x reference)
#include <cuda_runtime.h>
#include <cuda_bf16.h>
#include <cstdint>
#include <cstddef>

typedef __nv_bfloat16 bf16;

#define SEQ   2048
#define BATCH 2
#define DM    1024
#define NH    16
#define MTOT  (BATCH*SEQ)   // 4096

// ---------------------------------------------------------------------------
// Scratch (static device globals; allocation-guard safe)
// ---------------------------------------------------------------------------
__device__ float g_Vb[MTOT * DM];          // V projection, fp32 (pre-transpose)

__device__ bf16 g_Xhi[MTOT * DM];          // input hi/lo
__device__ bf16 g_Xlo[MTOT * DM];
__device__ bf16 g_Chi[MTOT * DM];          // ctx hi/lo (written by attention)
__device__ bf16 g_Clo[MTOT * DM];
__device__ bf16 g_WThi[4 * DM * DM];       // W transposed [n][k] hi/lo
__device__ bf16 g_WTlo[4 * DM * DM];

__device__ bf16 g_Qsh[MTOT * DM];          // Q proj (scaled) split, [bs][1024]
__device__ bf16 g_Qsl[MTOT * DM];
__device__ bf16 g_Ksh[MTOT * DM];          // K proj split, [bs][1024]
__device__ bf16 g_Ksl[MTOT * DM];
__device__ bf16 g_Vthi[BATCH * NH * 64 * SEQ];   // V^T per head: [bh][d][key]
__device__ bf16 g_Vtlo[BATCH * NH * 64 * SEQ];

// ---------------------------------------------------------------------------
// Portable-PTX helpers (base sm_103 target: mma.sync / ldmatrix / cp.async)
// ---------------------------------------------------------------------------
__device__ __forceinline__ uint32_t cvta_smem(const void* p) {
    uint32_t a;
    asm("{ .reg .u64 t; cvta.to.shared.u64 t, %1; cvt.u32.u64 %0, t; }"
        : "=r"(a) : "l"(p));
    return a;
}
__device__ __forceinline__ void cp16(uint32_t saddr, const void* gaddr) {
    asm volatile("cp.async.cg.shared.global [%0], [%1], 16;"
                 :: "r"(saddr), "l"(gaddr));
}
__device__ __forceinline__ void cp_commit() {
    asm volatile("cp.async.commit_group;");
}
__device__ __forceinline__ void ldm4(uint32_t* r, uint32_t addr) {
    asm volatile("ldmatrix.sync.aligned.m8n8.x4.shared.b16 {%0,%1,%2,%3}, [%4];"
                 : "=r"(r[0]), "=r"(r[1]), "=r"(r[2]), "=r"(r[3]) : "r"(addr));
}
__device__ __forceinline__ void mma_bf16(float* c, const uint32_t* a, const uint32_t* b) {
    asm volatile(
        "mma.sync.aligned.m16n8k16.row.col.f32.bf16.bf16.f32 "
        "{%0,%1,%2,%3}, {%4,%5,%6,%7}, {%8,%9}, {%0,%1,%2,%3};"
        : "+f"(c[0]), "+f"(c[1]), "+f"(c[2]), "+f"(c[3])
        : "r"(a[0]), "r"(a[1]), "r"(a[2]), "r"(a[3]), "r"(b[0]), "r"(b[1]));
}
__device__ __forceinline__ uint32_t pack_bf16(float a, float b) {
    __nv_bfloat162 t;
    t.x = __float2bfloat16(a);
    t.y = __float2bfloat16(b);
    return *(uint32_t*)&t;
}

// ---------------------------------------------------------------------------
// Conversion kernels
// ---------------------------------------------------------------------------
__global__ void conv_x_kernel(const float* __restrict__ X)
{
    int i = (blockIdx.x * 256 + threadIdx.x) * 4;
    float4 v = *(const float4*)(X + i);
    bf16 h0 = __float2bfloat16(v.x), h1 = __float2bfloat16(v.y);
    bf16 h2 = __float2bfloat16(v.z), h3 = __float2bfloat16(v.w);
    bf16 l0 = __float2bfloat16(v.x - __bfloat162float(h0));
    bf16 l1 = __float2bfloat16(v.y - __bfloat162float(h1));
    bf16 l2 = __float2bfloat16(v.z - __bfloat162float(h2));
    bf16 l3 = __float2bfloat16(v.w - __bfloat162float(h3));
    __nv_bfloat162 hh0; hh0.x = h0; hh0.y = h1;
    __nv_bfloat162 hh1; hh1.x = h2; hh1.y = h3;
    __nv_bfloat162 ll0; ll0.x = l0; ll0.y = l1;
    __nv_bfloat162 ll1; ll1.x = l2; ll1.y = l3;
    *(__nv_bfloat162*)(g_Xhi + i)     = hh0;
    *(__nv_bfloat162*)(g_Xhi + i + 2) = hh1;
    *(__nv_bfloat162*)(g_Xlo + i)     = ll0;
    *(__nv_bfloat162*)(g_Xlo + i + 2) = ll1;
}

// Transpose + convert weights: W[k][n] fp32 -> WT[n][k] bf16 hi/lo.
__global__ void conv_w_kernel(const float* __restrict__ Wq, const float* __restrict__ Wk,
                              const float* __restrict__ Wv, const float* __restrict__ Wo)
{
    __shared__ float t[32][33];
    int z = blockIdx.z;
    const float* W = (z == 0) ? Wq : (z == 1) ? Wk : (z == 2) ? Wv : Wo;
    bf16* Th = g_WThi + (size_t)z * DM * DM;
    bf16* Tl = g_WTlo + (size_t)z * DM * DM;
    int k0 = blockIdx.y * 32, n0 = blockIdx.x * 32;
    int tx = threadIdx.x & 31, ty = threadIdx.x >> 5;  // 32 x 8
#pragma unroll
    for (int i = 0; i < 4; i++)
        t[ty + 8 * i][tx] = W[(size_t)(k0 + ty + 8 * i) * DM + n0 + tx];
    __syncthreads();
#pragma unroll
    for (int i = 0; i < 4; i++) {
        float x = t[tx][ty + 8 * i];
        bf16 h = __float2bfloat16(x);
        size_t o = (size_t)(n0 + ty + 8 * i) * DM + k0 + tx;
        Th[o] = h;
        Tl[o] = __float2bfloat16(x - __bfloat162float(h));
    }
}

// Transpose + split V per head: g_Vb[bs][1024] -> g_Vt*[bh][d][key]
__global__ void conv_vt_kernel()
{
    __shared__ float t[32][33];
    int s0 = blockIdx.x * 32;          // key tile
    int d0 = blockIdx.y * 32;          // d tile (0 or 32)
    int bh = blockIdx.z;
    int b  = bh >> 4, h = bh & 15;
    int tx = threadIdx.x & 31, ty = threadIdx.x >> 5;  // 32 x 8
#pragma unroll
    for (int i = 0; i < 4; i++)
        t[ty + 8 * i][tx] = g_Vb[(size_t)(b * SEQ + s0 + ty + 8 * i) * DM + h * 64 + d0 + tx];
    __syncthreads();
#pragma unroll
    for (int i = 0; i < 4; i++) {
        float x = t[tx][ty + 8 * i];   // V[key=s0+tx][d=d0+ty+8i]
        bf16 hh = __float2bfloat16(x);
        size_t o = (size_t)bh * 64 * SEQ + (size_t)(d0 + ty + 8 * i) * SEQ + s0 + tx;
        g_Vthi[o] = hh;
        g_Vtlo[o] = __float2bfloat16(x - __bfloat162float(hh));
    }
}

// ---------------------------------------------------------------------------
// HMMA split-bf16 GEMM, 3-stage circular pipeline, ONE sync per stage.
// Output modes: Cf != nullptr -> fp32 (+bias); else split-bf16 (Chh, Cll).
// ---------------------------------------------------------------------------
#define BK          32
#define ASTRIDE     40
#define ARR_BYTES   (128 * ASTRIDE * 2)
#define STAGE_BYTES (4 * ARR_BYTES)
#define DYN_SMEM    (3 * STAGE_BYTES)      // 122880 B

__device__ __forceinline__ void g_load_stage(
    uint32_t sbase, int buf,
    const bf16* __restrict__ Ah, const bf16* __restrict__ Al,
    const bf16* __restrict__ Bh, const bf16* __restrict__ Bl,
    int m0, int n0, int k0, int tid)
{
    uint32_t sb = sbase + buf * STAGE_BYTES;
#pragma unroll
    for (int e = 0; e < 2; e++) {
        int lin = tid + 256 * e;
        int row = lin >> 2;
        int ch  = lin & 3;
        uint32_t soff = (uint32_t)(row * ASTRIDE + ch * 8) * 2;
        size_t gA = (size_t)(m0 + row) * DM + k0 + ch * 8;
        size_t gB = (size_t)(n0 + row) * DM + k0 + ch * 8;
        cp16(sb + soff,                 Ah + gA);
        cp16(sb + ARR_BYTES + soff,     Al + gA);
        cp16(sb + 2 * ARR_BYTES + soff, Bh + gB);
        cp16(sb + 3 * ARR_BYTES + soff, Bl + gB);
    }
    cp_commit();
}

__device__ __forceinline__ void g_compute_stage(
    uint32_t sbase, int buf, float (*acc)[4][4], int wm, int wn, int lane)
{
    uint32_t sb = sbase + buf * STAGE_BYTES;
#pragma unroll
    for (int ks = 0; ks < 2; ks++) {
        uint32_t ah[4][4], al[4][4];
#pragma unroll
        for (int mt = 0; mt < 4; mt++) {
            int row = wm * 64 + mt * 16 + (lane & 15);
            int ch  = ks * 2 + (lane >> 4);
            uint32_t ad = sb + (uint32_t)(row * ASTRIDE + ch * 8) * 2;
            ldm4(ah[mt], ad);
            ldm4(al[mt], ad + ARR_BYTES);
        }
        uint32_t bh[4][2], bl[4][2];
#pragma unroll
        for (int p = 0; p < 2; p++) {
            int row = wn * 32 + p * 16 + ((lane >> 4) << 3) + (lane & 7);
            int ch  = ks * 2 + ((lane >> 3) & 1);
            uint32_t bd = sb + 2 * ARR_BYTES + (uint32_t)(row * ASTRIDE + ch * 8) * 2;
            uint32_t r[4];
            ldm4(r, bd);
            bh[2 * p][0] = r[0]; bh[2 * p][1] = r[1];
            bh[2 * p + 1][0] = r[2]; bh[2 * p + 1][1] = r[3];
            ldm4(r, bd + ARR_BYTES);
            bl[2 * p][0] = r[0]; bl[2 * p][1] = r[1];
            bl[2 * p + 1][0] = r[2]; bl[2 * p + 1][1] = r[3];
        }
#pragma unroll
        for (int mt = 0; mt < 4; mt++)
#pragma unroll
            for (int nt = 0; nt < 4; nt++) {
                mma_bf16(acc[mt][nt], ah[mt], bh[nt]);
                mma_bf16(acc[mt][nt], ah[mt], bl[nt]);
                mma_bf16(acc[mt][nt], al[mt], bh[nt]);
            }
    }
}

__device__ __forceinline__ void gemm128_body(
    const bf16* __restrict__ Ah, const bf16* __restrict__ Al,
    const bf16* __restrict__ Bh, const bf16* __restrict__ Bl,
    float* __restrict__ Cf, bf16* __restrict__ Chh, bf16* __restrict__ Cll,
    const float* __restrict__ bias, float scale, int m0, int n0)
{
    extern __shared__ bf16 smem[];
    const int tid  = threadIdx.x;
    const int lane = tid & 31;
    const int wid  = tid >> 5;
    const int wm   = wid & 1;
    const int wn   = wid >> 1;
    uint32_t sbase = cvta_smem(smem);

    float acc[4][4][4];
#pragma unroll
    for (int i = 0; i < 4; i++)
#pragma unroll
        for (int j = 0; j < 4; j++)
#pragma unroll
            for (int k = 0; k < 4; k++) acc[i][j][k] = 0.f;

    g_load_stage(sbase, 0, Ah, Al, Bh, Bl, m0, n0, 0, tid);
    g_load_stage(sbase, 1, Ah, Al, Bh, Bl, m0, n0, BK, tid);

    const int NST = DM / BK;   // 32
    for (int s = 0; s < NST; s++) {
        if (s + 1 < NST) asm volatile("cp.async.wait_group 1;");
        else             asm volatile("cp.async.wait_group 0;");
        __syncthreads();
        // prefetch stage s+2 into the buffer stage s-1 used (all warps past it)
        if (s + 2 < NST)
            g_load_stage(sbase, (s + 2) % 3, Ah, Al, Bh, Bl, m0, n0, (s + 2) * BK, tid);
        g_compute_stage(sbase, s % 3, acc, wm, wn, lane);
    }

#pragma unroll
    for (int mt = 0; mt < 4; mt++) {
#pragma unroll
        for (int nt = 0; nt < 4; nt++) {
            int r = m0 + wm * 64 + mt * 16 + (lane >> 2);
            int c = n0 + wn * 32 + nt * 8 + (lane & 3) * 2;
            float x0 = acc[mt][nt][0] * scale, y0 = acc[mt][nt][1] * scale;
            float x1 = acc[mt][nt][2] * scale, y1 = acc[mt][nt][3] * scale;
            if (Cf) {
                if (bias) { x0 += bias[c]; y0 += bias[c + 1]; x1 += bias[c]; y1 += bias[c + 1]; }
                float2 v0; v0.x = x0; v0.y = y0;
                float2 v1; v1.x = x1; v1.y = y1;
                *(float2*)(Cf + (size_t)r * DM + c)       = v0;
                *(float2*)(Cf + (size_t)(r + 8) * DM + c) = v1;
            } else {
                bf16 hx0 = __float2bfloat16(x0), hy0 = __float2bfloat16(y0);
                bf16 hx1 = __float2bfloat16(x1), hy1 = __float2bfloat16(y1);
                __nv_bfloat162 h0; h0.x = hx0; h0.y = hy0;
                __nv_bfloat162 h1; h1.x = hx1; h1.y = hy1;
                __nv_bfloat162 l0; l0.x = __float2bfloat16(x0 - __bfloat162float(hx0));
                l0.y = __float2bfloat16(y0 - __bfloat162float(hy0));
                __nv_bfloat162 l1; l1.x = __float2bfloat16(x1 - __bfloat162float(hx1));
                l1.y = __float2bfloat16(y1 - __bfloat162float(hy1));
                *(__nv_bfloat162*)(Chh + (size_t)r * DM + c)       = h0;
                *(__nv_bfloat162*)(Chh + (size_t)(r + 8) * DM + c) = h1;
                *(__nv_bfloat162*)(Cll + (size_t)r * DM + c)       = l0;
                *(__nv_bfloat162*)(Cll + (size_t)(r + 8) * DM + c) = l1;
            }
        }
    }
}

__global__ __launch_bounds__(256)
void proj_mm_kernel()
{
    int z = blockIdx.z;
    const bf16* Bh = g_WThi + (size_t)z * DM * DM;
    const bf16* Bl = g_WTlo + (size_t)z * DM * DM;
    int m0 = blockIdx.y * 128, n0 = blockIdx.x * 128;
    if (z == 0)
        gemm128_body(g_Xhi, g_Xlo, Bh, Bl, nullptr, g_Qsh, g_Qsl, nullptr, 0.125f, m0, n0);
    else if (z == 1)
        gemm128_body(g_Xhi, g_Xlo, Bh, Bl, nullptr, g_Ksh, g_Ksl, nullptr, 1.0f, m0, n0);
    else
        gemm128_body(g_Xhi, g_Xlo, Bh, Bl, g_Vb, nullptr, nullptr, nullptr, 1.0f, m0, n0);
}

__global__ __launch_bounds__(256)
void out_mm_kernel(const float* __restrict__ bo, float* __restrict__ Y)
{
    gemm128_body(g_Chi, g_Clo,
                 g_WThi + (size_t)3 * DM * DM, g_WTlo + (size_t)3 * DM * DM,
                 Y, nullptr, nullptr, bo, 1.0f, blockIdx.y * 128, blockIdx.x * 128);
}

// ---------------------------------------------------------------------------
// FlashAttention-2 on mma.sync, split-bf16, 3-stage K/V pipeline,
// ONE sync per chunk, distance-2 prefetch. Ctx written split-bf16 directly.
// ---------------------------------------------------------------------------
#define ATP   72
#define ABUF_BYTES (4 * 64 * ATP * 2)      // K hi/lo + V hi/lo = 36864 B
#define AKH   0
#define AKL   4608
#define AVH   9216
#define AVL   13824
#define ATT_SMEM (3 * ABUF_BYTES)          // 110592 B

__device__ __forceinline__ void attn_load_kv(
    uint32_t sb, int buf, size_t kbase, size_t vbase, int kt, int tid)
{
    uint32_t sbb = sb + buf * ABUF_BYTES;
#pragma unroll
    for (int e = 0; e < 2; e++) {
        int lin = tid + 256 * e;       // 0..511
        int row = lin >> 3;            // 0..63
        int ch  = lin & 7;
        size_t gk = kbase + (size_t)(kt * 64 + row) * DM + ch * 8;
        size_t gv = vbase + (size_t)row * SEQ + kt * 64 + ch * 8;
        cp16(sbb + (uint32_t)(AKH + row * ATP + ch * 8) * 2, g_Ksh + gk);
        cp16(sbb + (uint32_t)(AKL + row * ATP + ch * 8) * 2, g_Ksl + gk);
        cp16(sbb + (uint32_t)(AVH + row * ATP + ch * 8) * 2, g_Vthi + gv);
        cp16(sbb + (uint32_t)(AVL + row * ATP + ch * 8) * 2, g_Vtlo + gv);
    }
    cp_commit();
}

__global__ __launch_bounds__(256)
void attn_mm_kernel()
{
    extern __shared__ bf16 asmem[];
    const int tid  = threadIdx.x;
    const int lane = tid & 31;
    const int w    = tid >> 5;
    const int bh   = blockIdx.x;
    const int b    = bh >> 4, h = bh & 15;
    const int q0   = blockIdx.y * 128;
    uint32_t sb = cvta_smem(asmem);

    // --- Stage Q tile (128 x 64, hi/lo) in buffer 0 region; load a-frags ---
#pragma unroll
    for (int e = 0; e < 4; e++) {
        int lin = tid + 256 * e;           // 0..1023
        int row = lin >> 3;                // 0..127
        int ch  = lin & 7;
        size_t g = (size_t)(b * SEQ + q0 + row) * DM + h * 64 + ch * 8;
        cp16(sb + (uint32_t)(row * ATP + ch * 8) * 2,          g_Qsh + g);
        cp16(sb + (uint32_t)(9216 + row * ATP + ch * 8) * 2,   g_Qsl + g);
    }
    cp_commit();
    asm volatile("cp.async.wait_group 0;");
    __syncthreads();

    uint32_t qh[4][4], ql[4][4];
#pragma unroll
    for (int ks = 0; ks < 4; ks++) {
        int row = w * 16 + (lane & 15);
        int ch  = ks * 2 + (lane >> 4);
        uint32_t ad = sb + (uint32_t)(row * ATP + ch * 8) * 2;
        ldm4(qh[ks], ad);
        ldm4(ql[ks], ad + 9216 * 2);
    }
    __syncthreads();   // Q consumed; smem becomes K/V triple buffer

    float o[8][4];
#pragma unroll
    for (int nt = 0; nt < 8; nt++)
#pragma unroll
        for (int k = 0; k < 4; k++) o[nt][k] = 0.f;
    float m0 = -1e30f, m1 = -1e30f, l0 = 0.f, l1 = 0.f;

    const size_t kbase = (size_t)(b * SEQ) * DM + h * 64;
    const size_t vbase = (size_t)bh * 64 * SEQ;
    const int NKT = SEQ / 64;

    attn_load_kv(sb, 0, kbase, vbase, 0, tid);
    attn_load_kv(sb, 1, kbase, vbase, 1, tid);

    for (int kt = 0; kt < NKT; kt++) {
        if (kt + 1 < NKT) asm volatile("cp.async.wait_group 1;");
        else              asm volatile("cp.async.wait_group 0;");
        __syncthreads();
        // prefetch chunk kt+2 into the buffer chunk kt-1 used
        if (kt + 2 < NKT)
            attn_load_kv(sb, (kt + 2) % 3, kbase, vbase, kt + 2, tid);
        uint32_t sbb = sb + (kt % 3) * ABUF_BYTES;

        // --- S = Q K^T ---
        float s[8][4];
#pragma unroll
        for (int nt = 0; nt < 8; nt++)
#pragma unroll
            for (int k = 0; k < 4; k++) s[nt][k] = 0.f;

#pragma unroll
        for (int ks = 0; ks < 4; ks++) {
            uint32_t kbh[8][2], kbl[8][2];
#pragma unroll
            for (int p = 0; p < 4; p++) {
                int row = p * 16 + ((lane >> 4) << 3) + (lane & 7);
                int ch  = ks * 2 + ((lane >> 3) & 1);
                uint32_t ad = sbb + (uint32_t)(AKH + row * ATP + ch * 8) * 2;
                uint32_t r[4];
                ldm4(r, ad);
                kbh[2 * p][0] = r[0]; kbh[2 * p][1] = r[1];
                kbh[2 * p + 1][0] = r[2]; kbh[2 * p + 1][1] = r[3];
                ldm4(r, ad + (AKL - AKH) * 2);
                kbl[2 * p][0] = r[0]; kbl[2 * p][1] = r[1];
                kbl[2 * p + 1][0] = r[2]; kbl[2 * p + 1][1] = r[3];
            }
#pragma unroll
            for (int nt = 0; nt < 8; nt++) {
                mma_bf16(s[nt], qh[ks], kbh[nt]);
                mma_bf16(s[nt], qh[ks], kbl[nt]);
                mma_bf16(s[nt], ql[ks], kbh[nt]);
            }
        }

        // --- online softmax (rows r0 = lane>>2, r1 = r0+8) ---
        float mx0 = -1e30f, mx1 = -1e30f;
#pragma unroll
        for (int nt = 0; nt < 8; nt++) {
            mx0 = fmaxf(mx0, fmaxf(s[nt][0], s[nt][1]));
            mx1 = fmaxf(mx1, fmaxf(s[nt][2], s[nt][3]));
        }
        mx0 = fmaxf(mx0, __shfl_xor_sync(0xffffffffu, mx0, 1));
        mx0 = fmaxf(mx0, __shfl_xor_sync(0xffffffffu, mx0, 2));
        mx1 = fmaxf(mx1, __shfl_xor_sync(0xffffffffu, mx1, 1));
        mx1 = fmaxf(mx1, __shfl_xor_sync(0xffffffffu, mx1, 2));
        float nm0 = fmaxf(m0, mx0), nm1 = fmaxf(m1, mx1);
        float c0 = __expf(m0 - nm0), c1 = __expf(m1 - nm1);
        m0 = nm0; m1 = nm1;
        float rs0 = 0.f, rs1 = 0.f;
#pragma unroll
        for (int nt = 0; nt < 8; nt++) {
            s[nt][0] = __expf(s[nt][0] - nm0);
            s[nt][1] = __expf(s[nt][1] - nm0);
            s[nt][2] = __expf(s[nt][2] - nm1);
            s[nt][3] = __expf(s[nt][3] - nm1);
            rs0 += s[nt][0] + s[nt][1];
            rs1 += s[nt][2] + s[nt][3];
        }
        rs0 += __shfl_xor_sync(0xffffffffu, rs0, 1);
        rs0 += __shfl_xor_sync(0xffffffffu, rs0, 2);
        rs1 += __shfl_xor_sync(0xffffffffu, rs1, 1);
        rs1 += __shfl_xor_sync(0xffffffffu, rs1, 2);
        l0 = l0 * c0 + rs0;
        l1 = l1 * c1 + rs1;
#pragma unroll
        for (int nt = 0; nt < 8; nt++) {
            o[nt][0] *= c0; o[nt][1] *= c0;
            o[nt][2] *= c1; o[nt][3] *= c1;
        }

        // --- P -> split-bf16 a-frags (register repack; no smem) ---
        uint32_t pha[4][4], pla[4][4];
#pragma unroll
        for (int g = 0; g < 4; g++) {
            int t0 = 2 * g, t1 = 2 * g + 1;
            pha[g][0] = pack_bf16(s[t0][0], s[t0][1]);
            pha[g][1] = pack_bf16(s[t0][2], s[t0][3]);
            pha[g][2] = pack_bf16(s[t1][0], s[t1][1]);
            pha[g][3] = pack_bf16(s[t1][2], s[t1][3]);
            float r00 = s[t0][0] - __bfloat162float(__float2bfloat16(s[t0][0]));
            float r01 = s[t0][1] - __bfloat162float(__float2bfloat16(s[t0][1]));
            float r02 = s[t0][2] - __bfloat162float(__float2bfloat16(s[t0][2]));
            float r03 = s[t0][3] - __bfloat162float(__float2bfloat16(s[t0][3]));
            float r10 = s[t1][0] - __bfloat162float(__float2bfloat16(s[t1][0]));
            float r11 = s[t1][1] - __bfloat162float(__float2bfloat16(s[t1][1]));
            float r12 = s[t1][2] - __bfloat162float(__float2bfloat16(s[t1][2]));
            float r13 = s[t1][3] - __bfloat162float(__float2bfloat16(s[t1][3]));
            pla[g][0] = pack_bf16(r00, r01);
            pla[g][1] = pack_bf16(r02, r03);
            pla[g][2] = pack_bf16(r10, r11);
            pla[g][3] = pack_bf16(r12, r13);
        }

        // --- O += P V ---
#pragma unroll
        for (int ks = 0; ks < 4; ks++) {
            uint32_t vbh[8][2], vbl[8][2];
#pragma unroll
            for (int p = 0; p < 4; p++) {
                int row = p * 16 + ((lane >> 4) << 3) + (lane & 7);
                int ch  = ks * 2 + ((lane >> 3) & 1);
                uint32_t ad = sbb + (uint32_t)(AVH + row * ATP + ch * 8) * 2;
                uint32_t r[4];
                ldm4(r, ad);
                vbh[2 * p][0] = r[0]; vbh[2 * p][1] = r[1];
                vbh[2 * p + 1][0] = r[2]; vbh[2 * p + 1][1] = r[3];
                ldm4(r, ad + (AVL - AVH) * 2);
                vbl[2 * p][0] = r[0]; vbl[2 * p][1] = r[1];
                vbl[2 * p + 1][0] = r[2]; vbl[2 * p + 1][1] = r[3];
            }
#pragma unroll
            for (int nt = 0; nt < 8; nt++) {
                mma_bf16(o[nt], pha[ks], vbh[nt]);
                mma_bf16(o[nt], pha[ks], vbl[nt]);
                mma_bf16(o[nt], pla[ks], vbh[nt]);
            }
        }
    }

    // --- normalize, split-convert, write ctx hi/lo directly ---
    float inv0 = 1.0f / l0, inv1 = 1.0f / l1;
    int r0 = q0 + w * 16 + (lane >> 2);
#pragma unroll
    for (int nt = 0; nt < 8; nt++) {
        int c = h * 64 + nt * 8 + (lane & 3) * 2;
        float x0 = o[nt][0] * inv0, y0 = o[nt][1] * inv0;
        float x1 = o[nt][2] * inv1, y1 = o[nt][3] * inv1;
        bf16 hx0 = __float2bfloat16(x0), hy0 = __float2bfloat16(y0);
        bf16 hx1 = __float2bfloat16(x1), hy1 = __float2bfloat16(y1);
        __nv_bfloat162 h0; h0.x = hx0; h0.y = hy0;
        __nv_bfloat162 h1; h1.x = hx1; h1.y = hy1;
        __nv_bfloat162 lo0; lo0.x = __float2bfloat16(x0 - __bfloat162float(hx0));
        lo0.y = __float2bfloat16(y0 - __bfloat162float(hy0));
        __nv_bfloat162 lo1; lo1.x = __float2bfloat16(x1 - __bfloat162float(hx1));
        lo1.y = __float2bfloat16(y1 - __bfloat162float(hy1));
        size_t base0 = (size_t)(b * SEQ + r0) * DM + c;
        size_t base1 = (size_t)(b * SEQ + r0 + 8) * DM + c;
        *(__nv_bfloat162*)(g_Chi + base0) = h0;
        *(__nv_bfloat162*)(g_Chi + base1) = h1;
        *(__nv_bfloat162*)(g_Clo + base0) = lo0;
        *(__nv_bfloat162*)(g_Clo + base1) = lo1;
    }
}

// ---------------------------------------------------------------------------
extern "C" void kernel_launch(void* const* d_in, const int* in_sizes, int n_in,
                              void* d_out, int out_size)
{
    const float* q  = (const float*)d_in[0];
    const float* Wq = (const float*)d_in[1];
    const float* Wk = (const float*)d_in[2];
    const float* Wv = (const float*)d_in[3];
    const float* Wo = (const float*)d_in[4];
    const float* bo = (const float*)d_in[5];

    cudaFuncSetAttribute(proj_mm_kernel, cudaFuncAttributeMaxDynamicSharedMemorySize, DYN_SMEM);
    cudaFuncSetAttribute(out_mm_kernel,  cudaFuncAttributeMaxDynamicSharedMemorySize, DYN_SMEM);
    cudaFuncSetAttribute(attn_mm_kernel, cudaFuncAttributeMaxDynamicSharedMemorySize, ATT_SMEM);

    // 1. split-bf16 conversion of input and (transposed) weights
    conv_x_kernel<<<MTOT * DM / 1024, 256>>>(q);
    conv_w_kernel<<<dim3(32, 32, 4), 256>>>(Wq, Wk, Wv, Wo);

    // 2. Q/K/V projections (Q pre-scaled; Q,K emitted split-bf16, V fp32)
    proj_mm_kernel<<<dim3(8, 32, 3), 256, DYN_SMEM>>>();

    // 3. V transpose + split per head
    conv_vt_kernel<<<dim3(SEQ / 32, 2, BATCH * NH), 256>>>();

    // 4. flash attention (3-stage K/V pipeline; ctx split-conversion fused)
    attn_mm_kernel<<<dim3(BATCH * NH, SEQ / 128), 256, ATT_SMEM>>>();

    // 5. output projection (+bias)
    out_mm_kernel<<<dim3(8, 32), 256, DYN_SMEM>>>(bo, (float*)d_out);
}

// round 13
// speedup vs baseline: 1.0727x; 1.0727x over previous
#include <cuda_runtime.h>
#include <cuda_bf16.h>
#include <cstdint>
#include <cstddef>

typedef __nv_bfloat16 bf16;

#define SEQ   2048
#define BATCH 2
#define DM    1024
#define NH    16
#define MTOT  (BATCH*SEQ)   // 4096

// ---------------------------------------------------------------------------
// Scratch (static device globals; allocation-guard safe)
// ---------------------------------------------------------------------------
__device__ float g_Vb[MTOT * DM];          // V projection, fp32 (pre-transpose)

__device__ bf16 g_Xhi[MTOT * DM];          // input hi/lo
__device__ bf16 g_Xlo[MTOT * DM];
__device__ bf16 g_Chi[MTOT * DM];          // ctx hi/lo (written by attention)
__device__ bf16 g_Clo[MTOT * DM];
__device__ bf16 g_WThi[4 * DM * DM];       // W transposed [n][k] hi/lo
__device__ bf16 g_WTlo[4 * DM * DM];

__device__ bf16 g_Qsh[MTOT * DM];          // Q proj (scaled) split, [bs][1024]
__device__ bf16 g_Qsl[MTOT * DM];
__device__ bf16 g_Ksh[MTOT * DM];          // K proj split, [bs][1024]
__device__ bf16 g_Ksl[MTOT * DM];
__device__ bf16 g_Vthi[BATCH * NH * 64 * SEQ];   // V^T per head: [bh][d][key]
__device__ bf16 g_Vtlo[BATCH * NH * 64 * SEQ];

// ---------------------------------------------------------------------------
// Portable-PTX helpers (base sm_103 target: mma.sync / ldmatrix / cp.async)
// ---------------------------------------------------------------------------
__device__ __forceinline__ uint32_t cvta_smem(const void* p) {
    uint32_t a;
    asm("{ .reg .u64 t; cvta.to.shared.u64 t, %1; cvt.u32.u64 %0, t; }"
        : "=r"(a) : "l"(p));
    return a;
}
__device__ __forceinline__ void cp16(uint32_t saddr, const void* gaddr) {
    asm volatile("cp.async.cg.shared.global [%0], [%1], 16;"
                 :: "r"(saddr), "l"(gaddr));
}
__device__ __forceinline__ void cp_commit() {
    asm volatile("cp.async.commit_group;");
}
__device__ __forceinline__ void ldm4(uint32_t* r, uint32_t addr) {
    asm volatile("ldmatrix.sync.aligned.m8n8.x4.shared.b16 {%0,%1,%2,%3}, [%4];"
                 : "=r"(r[0]), "=r"(r[1]), "=r"(r[2]), "=r"(r[3]) : "r"(addr));
}
__device__ __forceinline__ void mma_bf16(float* c, const uint32_t* a, const uint32_t* b) {
    asm volatile(
        "mma.sync.aligned.m16n8k16.row.col.f32.bf16.bf16.f32 "
        "{%0,%1,%2,%3}, {%4,%5,%6,%7}, {%8,%9}, {%0,%1,%2,%3};"
        : "+f"(c[0]), "+f"(c[1]), "+f"(c[2]), "+f"(c[3])
        : "r"(a[0]), "r"(a[1]), "r"(a[2]), "r"(a[3]), "r"(b[0]), "r"(b[1]));
}
__device__ __forceinline__ uint32_t pack_bf16(float a, float b) {
    __nv_bfloat162 t;
    t.x = __float2bfloat16(a);
    t.y = __float2bfloat16(b);
    return *(uint32_t*)&t;
}

// ---------------------------------------------------------------------------
// Conversion kernels
// ---------------------------------------------------------------------------
__global__ void conv_x_kernel(const float* __restrict__ X)
{
    int i = (blockIdx.x * 256 + threadIdx.x) * 4;
    float4 v = *(const float4*)(X + i);
    bf16 h0 = __float2bfloat16(v.x), h1 = __float2bfloat16(v.y);
    bf16 h2 = __float2bfloat16(v.z), h3 = __float2bfloat16(v.w);
    bf16 l0 = __float2bfloat16(v.x - __bfloat162float(h0));
    bf16 l1 = __float2bfloat16(v.y - __bfloat162float(h1));
    bf16 l2 = __float2bfloat16(v.z - __bfloat162float(h2));
    bf16 l3 = __float2bfloat16(v.w - __bfloat162float(h3));
    __nv_bfloat162 hh0; hh0.x = h0; hh0.y = h1;
    __nv_bfloat162 hh1; hh1.x = h2; hh1.y = h3;
    __nv_bfloat162 ll0; ll0.x = l0; ll0.y = l1;
    __nv_bfloat162 ll1; ll1.x = l2; ll1.y = l3;
    *(__nv_bfloat162*)(g_Xhi + i)     = hh0;
    *(__nv_bfloat162*)(g_Xhi + i + 2) = hh1;
    *(__nv_bfloat162*)(g_Xlo + i)     = ll0;
    *(__nv_bfloat162*)(g_Xlo + i + 2) = ll1;
}

// Transpose + convert weights: W[k][n] fp32 -> WT[n][k] bf16 hi/lo.
__global__ void conv_w_kernel(const float* __restrict__ Wq, const float* __restrict__ Wk,
                              const float* __restrict__ Wv, const float* __restrict__ Wo)
{
    __shared__ float t[32][33];
    int z = blockIdx.z;
    const float* W = (z == 0) ? Wq : (z == 1) ? Wk : (z == 2) ? Wv : Wo;
    bf16* Th = g_WThi + (size_t)z * DM * DM;
    bf16* Tl = g_WTlo + (size_t)z * DM * DM;
    int k0 = blockIdx.y * 32, n0 = blockIdx.x * 32;
    int tx = threadIdx.x & 31, ty = threadIdx.x >> 5;  // 32 x 8
#pragma unroll
    for (int i = 0; i < 4; i++)
        t[ty + 8 * i][tx] = W[(size_t)(k0 + ty + 8 * i) * DM + n0 + tx];
    __syncthreads();
#pragma unroll
    for (int i = 0; i < 4; i++) {
        float x = t[tx][ty + 8 * i];
        bf16 h = __float2bfloat16(x);
        size_t o = (size_t)(n0 + ty + 8 * i) * DM + k0 + tx;
        Th[o] = h;
        Tl[o] = __float2bfloat16(x - __bfloat162float(h));
    }
}

// Transpose + split V per head: g_Vb[bs][1024] -> g_Vt*[bh][d][key]
__global__ void conv_vt_kernel()
{
    __shared__ float t[32][33];
    int s0 = blockIdx.x * 32;          // key tile
    int d0 = blockIdx.y * 32;          // d tile (0 or 32)
    int bh = blockIdx.z;
    int b  = bh >> 4, h = bh & 15;
    int tx = threadIdx.x & 31, ty = threadIdx.x >> 5;  // 32 x 8
#pragma unroll
    for (int i = 0; i < 4; i++)
        t[ty + 8 * i][tx] = g_Vb[(size_t)(b * SEQ + s0 + ty + 8 * i) * DM + h * 64 + d0 + tx];
    __syncthreads();
#pragma unroll
    for (int i = 0; i < 4; i++) {
        float x = t[tx][ty + 8 * i];   // V[key=s0+tx][d=d0+ty+8i]
        bf16 hh = __float2bfloat16(x);
        size_t o = (size_t)bh * 64 * SEQ + (size_t)(d0 + ty + 8 * i) * SEQ + s0 + tx;
        g_Vthi[o] = hh;
        g_Vtlo[o] = __float2bfloat16(x - __bfloat162float(hh));
    }
}

// ---------------------------------------------------------------------------
// HMMA split-bf16 GEMM, 2-buffer single-sync pipeline:
//   per stage: wait_group 0 -> ONE __syncthreads -> issue load s+1 -> compute s
// Output modes: Cf != nullptr -> fp32 (+bias); else split-bf16 (Chh, Cll).
// ---------------------------------------------------------------------------
#define BK          32
#define ASTRIDE     40
#define ARR_BYTES   (128 * ASTRIDE * 2)
#define STAGE_BYTES (4 * ARR_BYTES)
#define DYN_SMEM    (2 * STAGE_BYTES)      // 81920 B

__device__ __forceinline__ void g_load_stage(
    uint32_t sbase, int buf,
    const bf16* __restrict__ Ah, const bf16* __restrict__ Al,
    const bf16* __restrict__ Bh, const bf16* __restrict__ Bl,
    int m0, int n0, int k0, int tid)
{
    uint32_t sb = sbase + buf * STAGE_BYTES;
#pragma unroll
    for (int e = 0; e < 2; e++) {
        int lin = tid + 256 * e;
        int row = lin >> 2;
        int ch  = lin & 3;
        uint32_t soff = (uint32_t)(row * ASTRIDE + ch * 8) * 2;
        size_t gA = (size_t)(m0 + row) * DM + k0 + ch * 8;
        size_t gB = (size_t)(n0 + row) * DM + k0 + ch * 8;
        cp16(sb + soff,                 Ah + gA);
        cp16(sb + ARR_BYTES + soff,     Al + gA);
        cp16(sb + 2 * ARR_BYTES + soff, Bh + gB);
        cp16(sb + 3 * ARR_BYTES + soff, Bl + gB);
    }
    cp_commit();
}

__device__ __forceinline__ void g_compute_stage(
    uint32_t sbase, int buf, float (*acc)[4][4], int wm, int wn, int lane)
{
    uint32_t sb = sbase + buf * STAGE_BYTES;
#pragma unroll
    for (int ks = 0; ks < 2; ks++) {
        uint32_t ah[4][4], al[4][4];
#pragma unroll
        for (int mt = 0; mt < 4; mt++) {
            int row = wm * 64 + mt * 16 + (lane & 15);
            int ch  = ks * 2 + (lane >> 4);
            uint32_t ad = sb + (uint32_t)(row * ASTRIDE + ch * 8) * 2;
            ldm4(ah[mt], ad);
            ldm4(al[mt], ad + ARR_BYTES);
        }
        uint32_t bh[4][2], bl[4][2];
#pragma unroll
        for (int p = 0; p < 2; p++) {
            int row = wn * 32 + p * 16 + ((lane >> 4) << 3) + (lane & 7);
            int ch  = ks * 2 + ((lane >> 3) & 1);
            uint32_t bd = sb + 2 * ARR_BYTES + (uint32_t)(row * ASTRIDE + ch * 8) * 2;
            uint32_t r[4];
            ldm4(r, bd);
            bh[2 * p][0] = r[0]; bh[2 * p][1] = r[1];
            bh[2 * p + 1][0] = r[2]; bh[2 * p + 1][1] = r[3];
            ldm4(r, bd + ARR_BYTES);
            bl[2 * p][0] = r[0]; bl[2 * p][1] = r[1];
            bl[2 * p + 1][0] = r[2]; bl[2 * p + 1][1] = r[3];
        }
#pragma unroll
        for (int mt = 0; mt < 4; mt++)
#pragma unroll
            for (int nt = 0; nt < 4; nt++) {
                mma_bf16(acc[mt][nt], ah[mt], bh[nt]);
                mma_bf16(acc[mt][nt], ah[mt], bl[nt]);
                mma_bf16(acc[mt][nt], al[mt], bh[nt]);
            }
    }
}

__device__ __forceinline__ void gemm128_body(
    const bf16* __restrict__ Ah, const bf16* __restrict__ Al,
    const bf16* __restrict__ Bh, const bf16* __restrict__ Bl,
    float* __restrict__ Cf, bf16* __restrict__ Chh, bf16* __restrict__ Cll,
    const float* __restrict__ bias, float scale, int m0, int n0)
{
    extern __shared__ bf16 smem[];
    const int tid  = threadIdx.x;
    const int lane = tid & 31;
    const int wid  = tid >> 5;
    const int wm   = wid & 1;
    const int wn   = wid >> 1;
    uint32_t sbase = cvta_smem(smem);

    float acc[4][4][4];
#pragma unroll
    for (int i = 0; i < 4; i++)
#pragma unroll
        for (int j = 0; j < 4; j++)
#pragma unroll
            for (int k = 0; k < 4; k++) acc[i][j][k] = 0.f;

    g_load_stage(sbase, 0, Ah, Al, Bh, Bl, m0, n0, 0, tid);

    const int NST = DM / BK;   // 32
    for (int s = 0; s < NST; s++) {
        asm volatile("cp.async.wait_group 0;");   // load s complete
        __syncthreads();                          // visible to all; buf s+1 free
        if (s + 1 < NST)
            g_load_stage(sbase, (s + 1) & 1, Ah, Al, Bh, Bl, m0, n0, (s + 1) * BK, tid);
        g_compute_stage(sbase, s & 1, acc, wm, wn, lane);
    }

#pragma unroll
    for (int mt = 0; mt < 4; mt++) {
#pragma unroll
        for (int nt = 0; nt < 4; nt++) {
            int r = m0 + wm * 64 + mt * 16 + (lane >> 2);
            int c = n0 + wn * 32 + nt * 8 + (lane & 3) * 2;
            float x0 = acc[mt][nt][0] * scale, y0 = acc[mt][nt][1] * scale;
            float x1 = acc[mt][nt][2] * scale, y1 = acc[mt][nt][3] * scale;
            if (Cf) {
                if (bias) { x0 += bias[c]; y0 += bias[c + 1]; x1 += bias[c]; y1 += bias[c + 1]; }
                float2 v0; v0.x = x0; v0.y = y0;
                float2 v1; v1.x = x1; v1.y = y1;
                *(float2*)(Cf + (size_t)r * DM + c)       = v0;
                *(float2*)(Cf + (size_t)(r + 8) * DM + c) = v1;
            } else {
                bf16 hx0 = __float2bfloat16(x0), hy0 = __float2bfloat16(y0);
                bf16 hx1 = __float2bfloat16(x1), hy1 = __float2bfloat16(y1);
                __nv_bfloat162 h0; h0.x = hx0; h0.y = hy0;
                __nv_bfloat162 h1; h1.x = hx1; h1.y = hy1;
                __nv_bfloat162 l0; l0.x = __float2bfloat16(x0 - __bfloat162float(hx0));
                l0.y = __float2bfloat16(y0 - __bfloat162float(hy0));
                __nv_bfloat162 l1; l1.x = __float2bfloat16(x1 - __bfloat162float(hx1));
                l1.y = __float2bfloat16(y1 - __bfloat162float(hy1));
                *(__nv_bfloat162*)(Chh + (size_t)r * DM + c)       = h0;
                *(__nv_bfloat162*)(Chh + (size_t)(r + 8) * DM + c) = h1;
                *(__nv_bfloat162*)(Cll + (size_t)r * DM + c)       = l0;
                *(__nv_bfloat162*)(Cll + (size_t)(r + 8) * DM + c) = l1;
            }
        }
    }
}

__global__ __launch_bounds__(256)
void proj_mm_kernel()
{
    int z = blockIdx.z;
    const bf16* Bh = g_WThi + (size_t)z * DM * DM;
    const bf16* Bl = g_WTlo + (size_t)z * DM * DM;
    int m0 = blockIdx.y * 128, n0 = blockIdx.x * 128;
    if (z == 0)
        gemm128_body(g_Xhi, g_Xlo, Bh, Bl, nullptr, g_Qsh, g_Qsl, nullptr, 0.125f, m0, n0);
    else if (z == 1)
        gemm128_body(g_Xhi, g_Xlo, Bh, Bl, nullptr, g_Ksh, g_Ksl, nullptr, 1.0f, m0, n0);
    else
        gemm128_body(g_Xhi, g_Xlo, Bh, Bl, g_Vb, nullptr, nullptr, nullptr, 1.0f, m0, n0);
}

__global__ __launch_bounds__(256)
void out_mm_kernel(const float* __restrict__ bo, float* __restrict__ Y)
{
    gemm128_body(g_Chi, g_Clo,
                 g_WThi + (size_t)3 * DM * DM, g_WTlo + (size_t)3 * DM * DM,
                 Y, nullptr, nullptr, bo, 1.0f, blockIdx.y * 128, blockIdx.x * 128);
}

// ---------------------------------------------------------------------------
// FlashAttention-2 on mma.sync, split-bf16, 2-buffer single-sync K/V pipeline.
// Block: one (b,h) x 128 queries, 8 warps x 16 q-rows. Ctx written split-bf16.
// ---------------------------------------------------------------------------
#define ATP   72
#define ABUF_BYTES (4 * 64 * ATP * 2)      // K hi/lo + V hi/lo = 36864 B
#define AKH   0
#define AKL   4608
#define AVH   9216
#define AVL   13824
#define ATT_SMEM (2 * ABUF_BYTES)          // 73728 B

__device__ __forceinline__ void attn_load_kv(
    uint32_t sb, int buf, size_t kbase, size_t vbase, int kt, int tid)
{
    uint32_t sbb = sb + buf * ABUF_BYTES;
#pragma unroll
    for (int e = 0; e < 2; e++) {
        int lin = tid + 256 * e;       // 0..511
        int row = lin >> 3;            // 0..63
        int ch  = lin & 7;
        size_t gk = kbase + (size_t)(kt * 64 + row) * DM + ch * 8;
        size_t gv = vbase + (size_t)row * SEQ + kt * 64 + ch * 8;
        cp16(sbb + (uint32_t)(AKH + row * ATP + ch * 8) * 2, g_Ksh + gk);
        cp16(sbb + (uint32_t)(AKL + row * ATP + ch * 8) * 2, g_Ksl + gk);
        cp16(sbb + (uint32_t)(AVH + row * ATP + ch * 8) * 2, g_Vthi + gv);
        cp16(sbb + (uint32_t)(AVL + row * ATP + ch * 8) * 2, g_Vtlo + gv);
    }
    cp_commit();
}

__global__ __launch_bounds__(256)
void attn_mm_kernel()
{
    extern __shared__ bf16 asmem[];
    const int tid  = threadIdx.x;
    const int lane = tid & 31;
    const int w    = tid >> 5;
    const int bh   = blockIdx.x;
    const int b    = bh >> 4, h = bh & 15;
    const int q0   = blockIdx.y * 128;
    uint32_t sb = cvta_smem(asmem);

    // --- Stage Q tile (128 x 64, hi/lo) in buffer 0 region; load a-frags ---
#pragma unroll
    for (int e = 0; e < 4; e++) {
        int lin = tid + 256 * e;           // 0..1023
        int row = lin >> 3;                // 0..127
        int ch  = lin & 7;
        size_t g = (size_t)(b * SEQ + q0 + row) * DM + h * 64 + ch * 8;
        cp16(sb + (uint32_t)(row * ATP + ch * 8) * 2,          g_Qsh + g);
        cp16(sb + (uint32_t)(9216 + row * ATP + ch * 8) * 2,   g_Qsl + g);
    }
    cp_commit();
    asm volatile("cp.async.wait_group 0;");
    __syncthreads();

    uint32_t qh[4][4], ql[4][4];
#pragma unroll
    for (int ks = 0; ks < 4; ks++) {
        int row = w * 16 + (lane & 15);
        int ch  = ks * 2 + (lane >> 4);
        uint32_t ad = sb + (uint32_t)(row * ATP + ch * 8) * 2;
        ldm4(qh[ks], ad);
        ldm4(ql[ks], ad + 9216 * 2);
    }
    __syncthreads();   // Q consumed; smem becomes K/V double buffer

    float o[8][4];
#pragma unroll
    for (int nt = 0; nt < 8; nt++)
#pragma unroll
        for (int k = 0; k < 4; k++) o[nt][k] = 0.f;
    float m0 = -1e30f, m1 = -1e30f, l0 = 0.f, l1 = 0.f;

    const size_t kbase = (size_t)(b * SEQ) * DM + h * 64;
    const size_t vbase = (size_t)bh * 64 * SEQ;
    const int NKT = SEQ / 64;

    attn_load_kv(sb, 0, kbase, vbase, 0, tid);

    for (int kt = 0; kt < NKT; kt++) {
        asm volatile("cp.async.wait_group 0;");   // load kt complete
        __syncthreads();                          // visible; buf kt+1 free
        if (kt + 1 < NKT)
            attn_load_kv(sb, (kt + 1) & 1, kbase, vbase, kt + 1, tid);
        uint32_t sbb = sb + (kt & 1) * ABUF_BYTES;

        // --- S = Q K^T ---
        float s[8][4];
#pragma unroll
        for (int nt = 0; nt < 8; nt++)
#pragma unroll
            for (int k = 0; k < 4; k++) s[nt][k] = 0.f;

#pragma unroll
        for (int ks = 0; ks < 4; ks++) {
            uint32_t kbh[8][2], kbl[8][2];
#pragma unroll
            for (int p = 0; p < 4; p++) {
                int row = p * 16 + ((lane >> 4) << 3) + (lane & 7);
                int ch  = ks * 2 + ((lane >> 3) & 1);
                uint32_t ad = sbb + (uint32_t)(AKH + row * ATP + ch * 8) * 2;
                uint32_t r[4];
                ldm4(r, ad);
                kbh[2 * p][0] = r[0]; kbh[2 * p][1] = r[1];
                kbh[2 * p + 1][0] = r[2]; kbh[2 * p + 1][1] = r[3];
                ldm4(r, ad + (AKL - AKH) * 2);
                kbl[2 * p][0] = r[0]; kbl[2 * p][1] = r[1];
                kbl[2 * p + 1][0] = r[2]; kbl[2 * p + 1][1] = r[3];
            }
#pragma unroll
            for (int nt = 0; nt < 8; nt++) {
                mma_bf16(s[nt], qh[ks], kbh[nt]);
                mma_bf16(s[nt], qh[ks], kbl[nt]);
                mma_bf16(s[nt], ql[ks], kbh[nt]);
            }
        }

        // --- online softmax (rows r0 = lane>>2, r1 = r0+8) ---
        float mx0 = -1e30f, mx1 = -1e30f;
#pragma unroll
        for (int nt = 0; nt < 8; nt++) {
            mx0 = fmaxf(mx0, fmaxf(s[nt][0], s[nt][1]));
            mx1 = fmaxf(mx1, fmaxf(s[nt][2], s[nt][3]));
        }
        mx0 = fmaxf(mx0, __shfl_xor_sync(0xffffffffu, mx0, 1));
        mx0 = fmaxf(mx0, __shfl_xor_sync(0xffffffffu, mx0, 2));
        mx1 = fmaxf(mx1, __shfl_xor_sync(0xffffffffu, mx1, 1));
        mx1 = fmaxf(mx1, __shfl_xor_sync(0xffffffffu, mx1, 2));
        float nm0 = fmaxf(m0, mx0), nm1 = fmaxf(m1, mx1);
        float c0 = __expf(m0 - nm0), c1 = __expf(m1 - nm1);
        m0 = nm0; m1 = nm1;
        float rs0 = 0.f, rs1 = 0.f;
#pragma unroll
        for (int nt = 0; nt < 8; nt++) {
            s[nt][0] = __expf(s[nt][0] - nm0);
            s[nt][1] = __expf(s[nt][1] - nm0);
            s[nt][2] = __expf(s[nt][2] - nm1);
            s[nt][3] = __expf(s[nt][3] - nm1);
            rs0 += s[nt][0] + s[nt][1];
            rs1 += s[nt][2] + s[nt][3];
        }
        rs0 += __shfl_xor_sync(0xffffffffu, rs0, 1);
        rs0 += __shfl_xor_sync(0xffffffffu, rs0, 2);
        rs1 += __shfl_xor_sync(0xffffffffu, rs1, 1);
        rs1 += __shfl_xor_sync(0xffffffffu, rs1, 2);
        l0 = l0 * c0 + rs0;
        l1 = l1 * c1 + rs1;
#pragma unroll
        for (int nt = 0; nt < 8; nt++) {
            o[nt][0] *= c0; o[nt][1] *= c0;
            o[nt][2] *= c1; o[nt][3] *= c1;
        }

        // --- P -> split-bf16 a-frags (register repack; no smem) ---
        uint32_t pha[4][4], pla[4][4];
#pragma unroll
        for (int g = 0; g < 4; g++) {
            int t0 = 2 * g, t1 = 2 * g + 1;
            pha[g][0] = pack_bf16(s[t0][0], s[t0][1]);
            pha[g][1] = pack_bf16(s[t0][2], s[t0][3]);
            pha[g][2] = pack_bf16(s[t1][0], s[t1][1]);
            pha[g][3] = pack_bf16(s[t1][2], s[t1][3]);
            float r00 = s[t0][0] - __bfloat162float(__float2bfloat16(s[t0][0]));
            float r01 = s[t0][1] - __bfloat162float(__float2bfloat16(s[t0][1]));
            float r02 = s[t0][2] - __bfloat162float(__float2bfloat16(s[t0][2]));
            float r03 = s[t0][3] - __bfloat162float(__float2bfloat16(s[t0][3]));
            float r10 = s[t1][0] - __bfloat162float(__float2bfloat16(s[t1][0]));
            float r11 = s[t1][1] - __bfloat162float(__float2bfloat16(s[t1][1]));
            float r12 = s[t1][2] - __bfloat162float(__float2bfloat16(s[t1][2]));
            float r13 = s[t1][3] - __bfloat162float(__float2bfloat16(s[t1][3]));
            pla[g][0] = pack_bf16(r00, r01);
            pla[g][1] = pack_bf16(r02, r03);
            pla[g][2] = pack_bf16(r10, r11);
            pla[g][3] = pack_bf16(r12, r13);
        }

        // --- O += P V ---
#pragma unroll
        for (int ks = 0; ks < 4; ks++) {
            uint32_t vbh[8][2], vbl[8][2];
#pragma unroll
            for (int p = 0; p < 4; p++) {
                int row = p * 16 + ((lane >> 4) << 3) + (lane & 7);
                int ch  = ks * 2 + ((lane >> 3) & 1);
                uint32_t ad = sbb + (uint32_t)(AVH + row * ATP + ch * 8) * 2;
                uint32_t r[4];
                ldm4(r, ad);
                vbh[2 * p][0] = r[0]; vbh[2 * p][1] = r[1];
                vbh[2 * p + 1][0] = r[2]; vbh[2 * p + 1][1] = r[3];
                ldm4(r, ad + (AVL - AVH) * 2);
                vbl[2 * p][0] = r[0]; vbl[2 * p][1] = r[1];
                vbl[2 * p + 1][0] = r[2]; vbl[2 * p + 1][1] = r[3];
            }
#pragma unroll
            for (int nt = 0; nt < 8; nt++) {
                mma_bf16(o[nt], pha[ks], vbh[nt]);
                mma_bf16(o[nt], pha[ks], vbl[nt]);
                mma_bf16(o[nt], pla[ks], vbh[nt]);
            }
        }
    }

    // --- normalize, split-convert, write ctx hi/lo directly ---
    float inv0 = 1.0f / l0, inv1 = 1.0f / l1;
    int r0 = q0 + w * 16 + (lane >> 2);
#pragma unroll
    for (int nt = 0; nt < 8; nt++) {
        int c = h * 64 + nt * 8 + (lane & 3) * 2;
        float x0 = o[nt][0] * inv0, y0 = o[nt][1] * inv0;
        float x1 = o[nt][2] * inv1, y1 = o[nt][3] * inv1;
        bf16 hx0 = __float2bfloat16(x0), hy0 = __float2bfloat16(y0);
        bf16 hx1 = __float2bfloat16(x1), hy1 = __float2bfloat16(y1);
        __nv_bfloat162 h0; h0.x = hx0; h0.y = hy0;
        __nv_bfloat162 h1; h1.x = hx1; h1.y = hy1;
        __nv_bfloat162 lo0; lo0.x = __float2bfloat16(x0 - __bfloat162float(hx0));
        lo0.y = __float2bfloat16(y0 - __bfloat162float(hy0));
        __nv_bfloat162 lo1; lo1.x = __float2bfloat16(x1 - __bfloat162float(hx1));
        lo1.y = __float2bfloat16(y1 - __bfloat162float(hy1));
        size_t base0 = (size_t)(b * SEQ + r0) * DM + c;
        size_t base1 = (size_t)(b * SEQ + r0 + 8) * DM + c;
        *(__nv_bfloat162*)(g_Chi + base0) = h0;
        *(__nv_bfloat162*)(g_Chi + base1) = h1;
        *(__nv_bfloat162*)(g_Clo + base0) = lo0;
        *(__nv_bfloat162*)(g_Clo + base1) = lo1;
    }
}

// ---------------------------------------------------------------------------
extern "C" void kernel_launch(void* const* d_in, const int* in_sizes, int n_in,
                              void* d_out, int out_size)
{
    const float* q  = (const float*)d_in[0];
    const float* Wq = (const float*)d_in[1];
    const float* Wk = (const float*)d_in[2];
    const float* Wv = (const float*)d_in[3];
    const float* Wo = (const float*)d_in[4];
    const float* bo = (const float*)d_in[5];

    cudaFuncSetAttribute(proj_mm_kernel, cudaFuncAttributeMaxDynamicSharedMemorySize, DYN_SMEM);
    cudaFuncSetAttribute(out_mm_kernel,  cudaFuncAttributeMaxDynamicSharedMemorySize, DYN_SMEM);
    cudaFuncSetAttribute(attn_mm_kernel, cudaFuncAttributeMaxDynamicSharedMemorySize, ATT_SMEM);

    // 1. split-bf16 conversion of input and (transposed) weights
    conv_x_kernel<<<MTOT * DM / 1024, 256>>>(q);
    conv_w_kernel<<<dim3(32, 32, 4), 256>>>(Wq, Wk, Wv, Wo);

    // 2. Q/K/V projections (Q pre-scaled; Q,K emitted split-bf16, V fp32)
    proj_mm_kernel<<<dim3(8, 32, 3), 256, DYN_SMEM>>>();

    // 3. V transpose + split per head
    conv_vt_kernel<<<dim3(SEQ / 32, 2, BATCH * NH), 256>>>();

    // 4. flash attention (2-buffer single-sync K/V pipeline; ctx fused)
    attn_mm_kernel<<<dim3(BATCH * NH, SEQ / 128), 256, ATT_SMEM>>>();

    // 5. output projection (+bias)
    out_mm_kernel<<<dim3(8, 32), 256, DYN_SMEM>>>(bo, (float*)d_out);
}

// round 14
// speedup vs baseline: 1.1564x; 1.0780x over previous
#include <cuda_runtime.h>
#include <cuda_bf16.h>
#include <cstdint>
#include <cstddef>

typedef __nv_bfloat16 bf16;

#define SEQ   2048
#define BATCH 2
#define DM    1024
#define NH    16
#define MTOT  (BATCH*SEQ)   // 4096

// ---------------------------------------------------------------------------
// Scratch (static device globals; allocation-guard safe)
// ---------------------------------------------------------------------------
__device__ float g_Vb[MTOT * DM];          // V projection, fp32 (pre-transpose)

__device__ bf16 g_Xhi[MTOT * DM];          // input hi/lo
__device__ bf16 g_Xlo[MTOT * DM];
__device__ bf16 g_Chi[MTOT * DM];          // ctx hi/lo (written by attention)
__device__ bf16 g_Clo[MTOT * DM];
__device__ bf16 g_WThi[4 * DM * DM];       // W transposed [n][k] hi/lo
__device__ bf16 g_WTlo[4 * DM * DM];

__device__ bf16 g_Qsh[MTOT * DM];          // Q proj (scaled) split, [bs][1024]
__device__ bf16 g_Qsl[MTOT * DM];
__device__ bf16 g_Ksh[MTOT * DM];          // K proj split, [bs][1024]
__device__ bf16 g_Ksl[MTOT * DM];
__device__ bf16 g_Vthi[BATCH * NH * 64 * SEQ];   // V^T per head: [bh][d][key]
__device__ bf16 g_Vtlo[BATCH * NH * 64 * SEQ];

// ---------------------------------------------------------------------------
// Portable-PTX helpers (base sm_103 target: mma.sync / ldmatrix / cp.async)
// ---------------------------------------------------------------------------
__device__ __forceinline__ uint32_t cvta_smem(const void* p) {
    uint32_t a;
    asm("{ .reg .u64 t; cvta.to.shared.u64 t, %1; cvt.u32.u64 %0, t; }"
        : "=r"(a) : "l"(p));
    return a;
}
__device__ __forceinline__ void cp16(uint32_t saddr, const void* gaddr) {
    asm volatile("cp.async.cg.shared.global [%0], [%1], 16;"
                 :: "r"(saddr), "l"(gaddr));
}
__device__ __forceinline__ void cp_commit() {
    asm volatile("cp.async.commit_group;");
}
__device__ __forceinline__ void ldm4(uint32_t* r, uint32_t addr) {
    asm volatile("ldmatrix.sync.aligned.m8n8.x4.shared.b16 {%0,%1,%2,%3}, [%4];"
                 : "=r"(r[0]), "=r"(r[1]), "=r"(r[2]), "=r"(r[3]) : "r"(addr));
}
__device__ __forceinline__ void mma_bf16(float* c, const uint32_t* a, const uint32_t* b) {
    asm volatile(
        "mma.sync.aligned.m16n8k16.row.col.f32.bf16.bf16.f32 "
        "{%0,%1,%2,%3}, {%4,%5,%6,%7}, {%8,%9}, {%0,%1,%2,%3};"
        : "+f"(c[0]), "+f"(c[1]), "+f"(c[2]), "+f"(c[3])
        : "r"(a[0]), "r"(a[1]), "r"(a[2]), "r"(a[3]), "r"(b[0]), "r"(b[1]));
}
__device__ __forceinline__ uint32_t pack_bf16(float a, float b) {
    __nv_bfloat162 t;
    t.x = __float2bfloat16(a);
    t.y = __float2bfloat16(b);
    return *(uint32_t*)&t;
}

// ---------------------------------------------------------------------------
// Conversion kernels
// ---------------------------------------------------------------------------
__global__ void conv_x_kernel(const float* __restrict__ X)
{
    int i = (blockIdx.x * 256 + threadIdx.x) * 4;
    float4 v = *(const float4*)(X + i);
    bf16 h0 = __float2bfloat16(v.x), h1 = __float2bfloat16(v.y);
    bf16 h2 = __float2bfloat16(v.z), h3 = __float2bfloat16(v.w);
    bf16 l0 = __float2bfloat16(v.x - __bfloat162float(h0));
    bf16 l1 = __float2bfloat16(v.y - __bfloat162float(h1));
    bf16 l2 = __float2bfloat16(v.z - __bfloat162float(h2));
    bf16 l3 = __float2bfloat16(v.w - __bfloat162float(h3));
    __nv_bfloat162 hh0; hh0.x = h0; hh0.y = h1;
    __nv_bfloat162 hh1; hh1.x = h2; hh1.y = h3;
    __nv_bfloat162 ll0; ll0.x = l0; ll0.y = l1;
    __nv_bfloat162 ll1; ll1.x = l2; ll1.y = l3;
    *(__nv_bfloat162*)(g_Xhi + i)     = hh0;
    *(__nv_bfloat162*)(g_Xhi + i + 2) = hh1;
    *(__nv_bfloat162*)(g_Xlo + i)     = ll0;
    *(__nv_bfloat162*)(g_Xlo + i + 2) = ll1;
}

// Transpose + convert weights: W[k][n] fp32 -> WT[n][k] bf16 hi/lo.
__global__ void conv_w_kernel(const float* __restrict__ Wq, const float* __restrict__ Wk,
                              const float* __restrict__ Wv, const float* __restrict__ Wo)
{
    __shared__ float t[32][33];
    int z = blockIdx.z;
    const float* W = (z == 0) ? Wq : (z == 1) ? Wk : (z == 2) ? Wv : Wo;
    bf16* Th = g_WThi + (size_t)z * DM * DM;
    bf16* Tl = g_WTlo + (size_t)z * DM * DM;
    int k0 = blockIdx.y * 32, n0 = blockIdx.x * 32;
    int tx = threadIdx.x & 31, ty = threadIdx.x >> 5;  // 32 x 8
#pragma unroll
    for (int i = 0; i < 4; i++)
        t[ty + 8 * i][tx] = W[(size_t)(k0 + ty + 8 * i) * DM + n0 + tx];
    __syncthreads();
#pragma unroll
    for (int i = 0; i < 4; i++) {
        float x = t[tx][ty + 8 * i];
        bf16 h = __float2bfloat16(x);
        size_t o = (size_t)(n0 + ty + 8 * i) * DM + k0 + tx;
        Th[o] = h;
        Tl[o] = __float2bfloat16(x - __bfloat162float(h));
    }
}

// Transpose + split V per head: g_Vb[bs][1024] -> g_Vt*[bh][d][key]
__global__ void conv_vt_kernel()
{
    __shared__ float t[32][33];
    int s0 = blockIdx.x * 32;          // key tile
    int d0 = blockIdx.y * 32;          // d tile (0 or 32)
    int bh = blockIdx.z;
    int b  = bh >> 4, h = bh & 15;
    int tx = threadIdx.x & 31, ty = threadIdx.x >> 5;  // 32 x 8
#pragma unroll
    for (int i = 0; i < 4; i++)
        t[ty + 8 * i][tx] = g_Vb[(size_t)(b * SEQ + s0 + ty + 8 * i) * DM + h * 64 + d0 + tx];
    __syncthreads();
#pragma unroll
    for (int i = 0; i < 4; i++) {
        float x = t[tx][ty + 8 * i];   // V[key=s0+tx][d=d0+ty+8i]
        bf16 hh = __float2bfloat16(x);
        size_t o = (size_t)bh * 64 * SEQ + (size_t)(d0 + ty + 8 * i) * SEQ + s0 + tx;
        g_Vthi[o] = hh;
        g_Vtlo[o] = __float2bfloat16(x - __bfloat162float(hh));
    }
}

// ---------------------------------------------------------------------------
// HMMA split-bf16 GEMM, 128 threads (4 warps, 2m x 2n), CTA tile 128x64.
// 2-buffer single-sync pipeline. Smaller CTAs -> 2-3 CTAs/SM so independent
// CTAs overlap each other's load-waits with MMAs.
// Output modes: Cf != nullptr -> fp32 (+bias); else split-bf16 (Chh, Cll).
// ---------------------------------------------------------------------------
#define BK          32
#define ASTRIDE     40
#define OA_HI       0
#define OA_LO       10240                  // 128 rows * 40 * 2B
#define OB_HI       20480
#define OB_LO       25600                  // B arrays: 64 rows * 40 * 2B = 5120
#define STAGE_BYTES 30720
#define DYN_SMEM    (2 * STAGE_BYTES)      // 61440 B

__device__ __forceinline__ void g_load_stage(
    uint32_t sbase, int buf,
    const bf16* __restrict__ Ah, const bf16* __restrict__ Al,
    const bf16* __restrict__ Bh, const bf16* __restrict__ Bl,
    int m0, int n0, int k0, int tid)
{
    uint32_t sb = sbase + buf * STAGE_BYTES;
    // A: 128 rows x 4 chunks (hi+lo)
#pragma unroll
    for (int e = 0; e < 4; e++) {
        int lin = tid + 128 * e;             // 0..511
        int row = lin >> 2;                  // 0..127
        int ch  = lin & 3;
        uint32_t soff = (uint32_t)(row * ASTRIDE + ch * 8) * 2;
        size_t gA = (size_t)(m0 + row) * DM + k0 + ch * 8;
        cp16(sb + OA_HI + soff, Ah + gA);
        cp16(sb + OA_LO + soff, Al + gA);
    }
    // B: 64 rows x 4 chunks (hi+lo)
#pragma unroll
    for (int e = 0; e < 2; e++) {
        int lin = tid + 128 * e;             // 0..255
        int row = lin >> 2;                  // 0..63
        int ch  = lin & 3;
        uint32_t soff = (uint32_t)(row * ASTRIDE + ch * 8) * 2;
        size_t gB = (size_t)(n0 + row) * DM + k0 + ch * 8;
        cp16(sb + OB_HI + soff, Bh + gB);
        cp16(sb + OB_LO + soff, Bl + gB);
    }
    cp_commit();
}

__device__ __forceinline__ void g_compute_stage(
    uint32_t sbase, int buf, float (*acc)[4][4], int wm, int wn, int lane)
{
    uint32_t sb = sbase + buf * STAGE_BYTES;
#pragma unroll
    for (int ks = 0; ks < 2; ks++) {
        uint32_t ah[4][4], al[4][4];
#pragma unroll
        for (int mt = 0; mt < 4; mt++) {
            int row = wm * 64 + mt * 16 + (lane & 15);
            int ch  = ks * 2 + (lane >> 4);
            uint32_t ad = sb + OA_HI + (uint32_t)(row * ASTRIDE + ch * 8) * 2;
            ldm4(ah[mt], ad);
            ldm4(al[mt], ad + (OA_LO - OA_HI));
        }
        uint32_t bh[4][2], bl[4][2];
#pragma unroll
        for (int p = 0; p < 2; p++) {
            int row = wn * 32 + p * 16 + ((lane >> 4) << 3) + (lane & 7);
            int ch  = ks * 2 + ((lane >> 3) & 1);
            uint32_t bd = sb + OB_HI + (uint32_t)(row * ASTRIDE + ch * 8) * 2;
            uint32_t r[4];
            ldm4(r, bd);
            bh[2 * p][0] = r[0]; bh[2 * p][1] = r[1];
            bh[2 * p + 1][0] = r[2]; bh[2 * p + 1][1] = r[3];
            ldm4(r, bd + (OB_LO - OB_HI));
            bl[2 * p][0] = r[0]; bl[2 * p][1] = r[1];
            bl[2 * p + 1][0] = r[2]; bl[2 * p + 1][1] = r[3];
        }
#pragma unroll
        for (int mt = 0; mt < 4; mt++)
#pragma unroll
            for (int nt = 0; nt < 4; nt++) {
                mma_bf16(acc[mt][nt], ah[mt], bh[nt]);
                mma_bf16(acc[mt][nt], ah[mt], bl[nt]);
                mma_bf16(acc[mt][nt], al[mt], bh[nt]);
            }
    }
}

__device__ __forceinline__ void gemm128_body(
    const bf16* __restrict__ Ah, const bf16* __restrict__ Al,
    const bf16* __restrict__ Bh, const bf16* __restrict__ Bl,
    float* __restrict__ Cf, bf16* __restrict__ Chh, bf16* __restrict__ Cll,
    const float* __restrict__ bias, float scale, int m0, int n0)
{
    extern __shared__ bf16 smem[];
    const int tid  = threadIdx.x;
    const int lane = tid & 31;
    const int wid  = tid >> 5;       // 0..3
    const int wm   = wid & 1;        // m half (64 rows)
    const int wn   = wid >> 1;       // n half (32 cols)
    uint32_t sbase = cvta_smem(smem);

    float acc[4][4][4];
#pragma unroll
    for (int i = 0; i < 4; i++)
#pragma unroll
        for (int j = 0; j < 4; j++)
#pragma unroll
            for (int k = 0; k < 4; k++) acc[i][j][k] = 0.f;

    g_load_stage(sbase, 0, Ah, Al, Bh, Bl, m0, n0, 0, tid);

    const int NST = DM / BK;   // 32
    for (int s = 0; s < NST; s++) {
        asm volatile("cp.async.wait_group 0;");   // load s complete
        __syncthreads();                          // visible to all; buf s+1 free
        if (s + 1 < NST)
            g_load_stage(sbase, (s + 1) & 1, Ah, Al, Bh, Bl, m0, n0, (s + 1) * BK, tid);
        g_compute_stage(sbase, s & 1, acc, wm, wn, lane);
    }

#pragma unroll
    for (int mt = 0; mt < 4; mt++) {
#pragma unroll
        for (int nt = 0; nt < 4; nt++) {
            int r = m0 + wm * 64 + mt * 16 + (lane >> 2);
            int c = n0 + wn * 32 + nt * 8 + (lane & 3) * 2;
            float x0 = acc[mt][nt][0] * scale, y0 = acc[mt][nt][1] * scale;
            float x1 = acc[mt][nt][2] * scale, y1 = acc[mt][nt][3] * scale;
            if (Cf) {
                if (bias) { x0 += bias[c]; y0 += bias[c + 1]; x1 += bias[c]; y1 += bias[c + 1]; }
                float2 v0; v0.x = x0; v0.y = y0;
                float2 v1; v1.x = x1; v1.y = y1;
                *(float2*)(Cf + (size_t)r * DM + c)       = v0;
                *(float2*)(Cf + (size_t)(r + 8) * DM + c) = v1;
            } else {
                bf16 hx0 = __float2bfloat16(x0), hy0 = __float2bfloat16(y0);
                bf16 hx1 = __float2bfloat16(x1), hy1 = __float2bfloat16(y1);
                __nv_bfloat162 h0; h0.x = hx0; h0.y = hy0;
                __nv_bfloat162 h1; h1.x = hx1; h1.y = hy1;
                __nv_bfloat162 l0; l0.x = __float2bfloat16(x0 - __bfloat162float(hx0));
                l0.y = __float2bfloat16(y0 - __bfloat162float(hy0));
                __nv_bfloat162 l1; l1.x = __float2bfloat16(x1 - __bfloat162float(hx1));
                l1.y = __float2bfloat16(y1 - __bfloat162float(hy1));
                *(__nv_bfloat162*)(Chh + (size_t)r * DM + c)       = h0;
                *(__nv_bfloat162*)(Chh + (size_t)(r + 8) * DM + c) = h1;
                *(__nv_bfloat162*)(Cll + (size_t)r * DM + c)       = l0;
                *(__nv_bfloat162*)(Cll + (size_t)(r + 8) * DM + c) = l1;
            }
        }
    }
}

__global__ __launch_bounds__(128)
void proj_mm_kernel()
{
    int z = blockIdx.z;
    const bf16* Bh = g_WThi + (size_t)z * DM * DM;
    const bf16* Bl = g_WTlo + (size_t)z * DM * DM;
    int m0 = blockIdx.y * 128, n0 = blockIdx.x * 64;
    if (z == 0)
        gemm128_body(g_Xhi, g_Xlo, Bh, Bl, nullptr, g_Qsh, g_Qsl, nullptr, 0.125f, m0, n0);
    else if (z == 1)
        gemm128_body(g_Xhi, g_Xlo, Bh, Bl, nullptr, g_Ksh, g_Ksl, nullptr, 1.0f, m0, n0);
    else
        gemm128_body(g_Xhi, g_Xlo, Bh, Bl, g_Vb, nullptr, nullptr, nullptr, 1.0f, m0, n0);
}

__global__ __launch_bounds__(128)
void out_mm_kernel(const float* __restrict__ bo, float* __restrict__ Y)
{
    gemm128_body(g_Chi, g_Clo,
                 g_WThi + (size_t)3 * DM * DM, g_WTlo + (size_t)3 * DM * DM,
                 Y, nullptr, nullptr, bo, 1.0f, blockIdx.y * 128, blockIdx.x * 64);
}

// ---------------------------------------------------------------------------
// FlashAttention-2 on mma.sync, split-bf16, 2-buffer single-sync K/V pipeline.
// 128 threads (4 warps x 16 q-rows = 64-query tile) -> 2 CTAs/SM so the
// softmax phase of one CTA overlaps the MMA phase of the other.
// ---------------------------------------------------------------------------
#define ATP   72
#define ABUF_BYTES (4 * 64 * ATP * 2)      // K hi/lo + V hi/lo = 36864 B
#define AKH   0
#define AKL   4608
#define AVH   9216
#define AVL   13824
#define AQLO  4608                          // Q lo element offset (64 rows)
#define ATT_SMEM (2 * ABUF_BYTES)          // 73728 B

__device__ __forceinline__ void attn_load_kv(
    uint32_t sb, int buf, size_t kbase, size_t vbase, int kt, int tid)
{
    uint32_t sbb = sb + buf * ABUF_BYTES;
#pragma unroll
    for (int e = 0; e < 4; e++) {
        int lin = tid + 128 * e;       // 0..511
        int row = lin >> 3;            // 0..63
        int ch  = lin & 7;
        size_t gk = kbase + (size_t)(kt * 64 + row) * DM + ch * 8;
        size_t gv = vbase + (size_t)row * SEQ + kt * 64 + ch * 8;
        cp16(sbb + (uint32_t)(AKH + row * ATP + ch * 8) * 2, g_Ksh + gk);
        cp16(sbb + (uint32_t)(AKL + row * ATP + ch * 8) * 2, g_Ksl + gk);
        cp16(sbb + (uint32_t)(AVH + row * ATP + ch * 8) * 2, g_Vthi + gv);
        cp16(sbb + (uint32_t)(AVL + row * ATP + ch * 8) * 2, g_Vtlo + gv);
    }
    cp_commit();
}

__global__ __launch_bounds__(128)
void attn_mm_kernel()
{
    extern __shared__ bf16 asmem[];
    const int tid  = threadIdx.x;
    const int lane = tid & 31;
    const int w    = tid >> 5;         // 0..3
    const int bh   = blockIdx.x;
    const int b    = bh >> 4, h = bh & 15;
    const int q0   = blockIdx.y * 64;
    uint32_t sb = cvta_smem(asmem);

    // --- Stage Q tile (64 x 64, hi/lo) in buffer 0 region; load a-frags ---
#pragma unroll
    for (int e = 0; e < 4; e++) {
        int lin = tid + 128 * e;           // 0..511
        int row = lin >> 3;                // 0..63
        int ch  = lin & 7;
        size_t g = (size_t)(b * SEQ + q0 + row) * DM + h * 64 + ch * 8;
        cp16(sb + (uint32_t)(row * ATP + ch * 8) * 2,          g_Qsh + g);
        cp16(sb + (uint32_t)(AQLO + row * ATP + ch * 8) * 2,   g_Qsl + g);
    }
    cp_commit();
    asm volatile("cp.async.wait_group 0;");
    __syncthreads();

    uint32_t qh[4][4], ql[4][4];
#pragma unroll
    for (int ks = 0; ks < 4; ks++) {
        int row = w * 16 + (lane & 15);
        int ch  = ks * 2 + (lane >> 4);
        uint32_t ad = sb + (uint32_t)(row * ATP + ch * 8) * 2;
        ldm4(qh[ks], ad);
        ldm4(ql[ks], ad + AQLO * 2);
    }
    __syncthreads();   // Q consumed; smem becomes K/V double buffer

    float o[8][4];
#pragma unroll
    for (int nt = 0; nt < 8; nt++)
#pragma unroll
        for (int k = 0; k < 4; k++) o[nt][k] = 0.f;
    float m0 = -1e30f, m1 = -1e30f, l0 = 0.f, l1 = 0.f;

    const size_t kbase = (size_t)(b * SEQ) * DM + h * 64;
    const size_t vbase = (size_t)bh * 64 * SEQ;
    const int NKT = SEQ / 64;

    attn_load_kv(sb, 0, kbase, vbase, 0, tid);

    for (int kt = 0; kt < NKT; kt++) {
        asm volatile("cp.async.wait_group 0;");   // load kt complete
        __syncthreads();                          // visible; buf kt+1 free
        if (kt + 1 < NKT)
            attn_load_kv(sb, (kt + 1) & 1, kbase, vbase, kt + 1, tid);
        uint32_t sbb = sb + (kt & 1) * ABUF_BYTES;

        // --- S = Q K^T ---
        float s[8][4];
#pragma unroll
        for (int nt = 0; nt < 8; nt++)
#pragma unroll
            for (int k = 0; k < 4; k++) s[nt][k] = 0.f;

#pragma unroll
        for (int ks = 0; ks < 4; ks++) {
            uint32_t kbh[8][2], kbl[8][2];
#pragma unroll
            for (int p = 0; p < 4; p++) {
                int row = p * 16 + ((lane >> 4) << 3) + (lane & 7);
                int ch  = ks * 2 + ((lane >> 3) & 1);
                uint32_t ad = sbb + (uint32_t)(AKH + row * ATP + ch * 8) * 2;
                uint32_t r[4];
                ldm4(r, ad);
                kbh[2 * p][0] = r[0]; kbh[2 * p][1] = r[1];
                kbh[2 * p + 1][0] = r[2]; kbh[2 * p + 1][1] = r[3];
                ldm4(r, ad + (AKL - AKH) * 2);
                kbl[2 * p][0] = r[0]; kbl[2 * p][1] = r[1];
                kbl[2 * p + 1][0] = r[2]; kbl[2 * p + 1][1] = r[3];
            }
#pragma unroll
            for (int nt = 0; nt < 8; nt++) {
                mma_bf16(s[nt], qh[ks], kbh[nt]);
                mma_bf16(s[nt], qh[ks], kbl[nt]);
                mma_bf16(s[nt], ql[ks], kbh[nt]);
            }
        }

        // --- online softmax (rows r0 = lane>>2, r1 = r0+8) ---
        float mx0 = -1e30f, mx1 = -1e30f;
#pragma unroll
        for (int nt = 0; nt < 8; nt++) {
            mx0 = fmaxf(mx0, fmaxf(s[nt][0], s[nt][1]));
            mx1 = fmaxf(mx1, fmaxf(s[nt][2], s[nt][3]));
        }
        mx0 = fmaxf(mx0, __shfl_xor_sync(0xffffffffu, mx0, 1));
        mx0 = fmaxf(mx0, __shfl_xor_sync(0xffffffffu, mx0, 2));
        mx1 = fmaxf(mx1, __shfl_xor_sync(0xffffffffu, mx1, 1));
        mx1 = fmaxf(mx1, __shfl_xor_sync(0xffffffffu, mx1, 2));
        float nm0 = fmaxf(m0, mx0), nm1 = fmaxf(m1, mx1);
        float c0 = __expf(m0 - nm0), c1 = __expf(m1 - nm1);
        m0 = nm0; m1 = nm1;
        float rs0 = 0.f, rs1 = 0.f;
#pragma unroll
        for (int nt = 0; nt < 8; nt++) {
            s[nt][0] = __expf(s[nt][0] - nm0);
            s[nt][1] = __expf(s[nt][1] - nm0);
            s[nt][2] = __expf(s[nt][2] - nm1);
            s[nt][3] = __expf(s[nt][3] - nm1);
            rs0 += s[nt][0] + s[nt][1];
            rs1 += s[nt][2] + s[nt][3];
        }
        rs0 += __shfl_xor_sync(0xffffffffu, rs0, 1);
        rs0 += __shfl_xor_sync(0xffffffffu, rs0, 2);
        rs1 += __shfl_xor_sync(0xffffffffu, rs1, 1);
        rs1 += __shfl_xor_sync(0xffffffffu, rs1, 2);
        l0 = l0 * c0 + rs0;
        l1 = l1 * c1 + rs1;
#pragma unroll
        for (int nt = 0; nt < 8; nt++) {
            o[nt][0] *= c0; o[nt][1] *= c0;
            o[nt][2] *= c1; o[nt][3] *= c1;
        }

        // --- P -> split-bf16 a-frags (register repack; no smem) ---
        uint32_t pha[4][4], pla[4][4];
#pragma unroll
        for (int g = 0; g < 4; g++) {
            int t0 = 2 * g, t1 = 2 * g + 1;
            pha[g][0] = pack_bf16(s[t0][0], s[t0][1]);
            pha[g][1] = pack_bf16(s[t0][2], s[t0][3]);
            pha[g][2] = pack_bf16(s[t1][0], s[t1][1]);
            pha[g][3] = pack_bf16(s[t1][2], s[t1][3]);
            float r00 = s[t0][0] - __bfloat162float(__float2bfloat16(s[t0][0]));
            float r01 = s[t0][1] - __bfloat162float(__float2bfloat16(s[t0][1]));
            float r02 = s[t0][2] - __bfloat162float(__float2bfloat16(s[t0][2]));
            float r03 = s[t0][3] - __bfloat162float(__float2bfloat16(s[t0][3]));
            float r10 = s[t1][0] - __bfloat162float(__float2bfloat16(s[t1][0]));
            float r11 = s[t1][1] - __bfloat162float(__float2bfloat16(s[t1][1]));
            float r12 = s[t1][2] - __bfloat162float(__float2bfloat16(s[t1][2]));
            float r13 = s[t1][3] - __bfloat162float(__float2bfloat16(s[t1][3]));
            pla[g][0] = pack_bf16(r00, r01);
            pla[g][1] = pack_bf16(r02, r03);
            pla[g][2] = pack_bf16(r10, r11);
            pla[g][3] = pack_bf16(r12, r13);
        }

        // --- O += P V ---
#pragma unroll
        for (int ks = 0; ks < 4; ks++) {
            uint32_t vbh[8][2], vbl[8][2];
#pragma unroll
            for (int p = 0; p < 4; p++) {
                int row = p * 16 + ((lane >> 4) << 3) + (lane & 7);
                int ch  = ks * 2 + ((lane >> 3) & 1);
                uint32_t ad = sbb + (uint32_t)(AVH + row * ATP + ch * 8) * 2;
                uint32_t r[4];
                ldm4(r, ad);
                vbh[2 * p][0] = r[0]; vbh[2 * p][1] = r[1];
                vbh[2 * p + 1][0] = r[2]; vbh[2 * p + 1][1] = r[3];
                ldm4(r, ad + (AVL - AVH) * 2);
                vbl[2 * p][0] = r[0]; vbl[2 * p][1] = r[1];
                vbl[2 * p + 1][0] = r[2]; vbl[2 * p + 1][1] = r[3];
            }
#pragma unroll
            for (int nt = 0; nt < 8; nt++) {
                mma_bf16(o[nt], pha[ks], vbh[nt]);
                mma_bf16(o[nt], pha[ks], vbl[nt]);
                mma_bf16(o[nt], pla[ks], vbh[nt]);
            }
        }
    }

    // --- normalize, split-convert, write ctx hi/lo directly ---
    float inv0 = 1.0f / l0, inv1 = 1.0f / l1;
    int r0 = q0 + w * 16 + (lane >> 2);
#pragma unroll
    for (int nt = 0; nt < 8; nt++) {
        int c = h * 64 + nt * 8 + (lane & 3) * 2;
        float x0 = o[nt][0] * inv0, y0 = o[nt][1] * inv0;
        float x1 = o[nt][2] * inv1, y1 = o[nt][3] * inv1;
        bf16 hx0 = __float2bfloat16(x0), hy0 = __float2bfloat16(y0);
        bf16 hx1 = __float2bfloat16(x1), hy1 = __float2bfloat16(y1);
        __nv_bfloat162 h0; h0.x = hx0; h0.y = hy0;
        __nv_bfloat162 h1; h1.x = hx1; h1.y = hy1;
        __nv_bfloat162 lo0; lo0.x = __float2bfloat16(x0 - __bfloat162float(hx0));
        lo0.y = __float2bfloat16(y0 - __bfloat162float(hy0));
        __nv_bfloat162 lo1; lo1.x = __float2bfloat16(x1 - __bfloat162float(hx1));
        lo1.y = __float2bfloat16(y1 - __bfloat162float(hy1));
        size_t base0 = (size_t)(b * SEQ + r0) * DM + c;
        size_t base1 = (size_t)(b * SEQ + r0 + 8) * DM + c;
        *(__nv_bfloat162*)(g_Chi + base0) = h0;
        *(__nv_bfloat162*)(g_Chi + base1) = h1;
        *(__nv_bfloat162*)(g_Clo + base0) = lo0;
        *(__nv_bfloat162*)(g_Clo + base1) = lo1;
    }
}

// ---------------------------------------------------------------------------
extern "C" void kernel_launch(void* const* d_in, const int* in_sizes, int n_in,
                              void* d_out, int out_size)
{
    const float* q  = (const float*)d_in[0];
    const float* Wq = (const float*)d_in[1];
    const float* Wk = (const float*)d_in[2];
    const float* Wv = (const float*)d_in[3];
    const float* Wo = (const float*)d_in[4];
    const float* bo = (const float*)d_in[5];

    cudaFuncSetAttribute(proj_mm_kernel, cudaFuncAttributeMaxDynamicSharedMemorySize, DYN_SMEM);
    cudaFuncSetAttribute(out_mm_kernel,  cudaFuncAttributeMaxDynamicSharedMemorySize, DYN_SMEM);
    cudaFuncSetAttribute(attn_mm_kernel, cudaFuncAttributeMaxDynamicSharedMemorySize, ATT_SMEM);

    // 1. split-bf16 conversion of input and (transposed) weights
    conv_x_kernel<<<MTOT * DM / 1024, 256>>>(q);
    conv_w_kernel<<<dim3(32, 32, 4), 256>>>(Wq, Wk, Wv, Wo);

    // 2. Q/K/V projections (Q pre-scaled; Q,K emitted split-bf16, V fp32)
    proj_mm_kernel<<<dim3(16, 32, 3), 128, DYN_SMEM>>>();

    // 3. V transpose + split per head
    conv_vt_kernel<<<dim3(SEQ / 32, 2, BATCH * NH), 256>>>();

    // 4. flash attention (64-query CTAs; 2 CTAs/SM phase overlap)
    attn_mm_kernel<<<dim3(BATCH * NH, SEQ / 64), 128, ATT_SMEM>>>();

    // 5. output projection (+bias)
    out_mm_kernel<<<dim3(16, 32), 128, DYN_SMEM>>>(bo, (float*)d_out);
}

// round 15
// speedup vs baseline: 1.1849x; 1.0246x over previous
#include <cuda_runtime.h>
#include <cuda_bf16.h>
#include <cstdint>
#include <cstddef>

typedef __nv_bfloat16 bf16;

#define SEQ   2048
#define BATCH 2
#define DM    1024
#define NH    16
#define MTOT  (BATCH*SEQ)   // 4096

// ---------------------------------------------------------------------------
// Scratch (static device globals; allocation-guard safe)
// ---------------------------------------------------------------------------
__device__ float g_Vb[MTOT * DM];          // V projection, fp32 (pre-transpose)

__device__ bf16 g_Xhi[MTOT * DM];          // input hi/lo
__device__ bf16 g_Xlo[MTOT * DM];
__device__ bf16 g_Chi[MTOT * DM];          // ctx hi/lo (written by attention)
__device__ bf16 g_Clo[MTOT * DM];
__device__ bf16 g_WThi[4 * DM * DM];       // W transposed [n][k] hi/lo
__device__ bf16 g_WTlo[4 * DM * DM];

__device__ bf16 g_Qsh[MTOT * DM];          // Q proj (scaled) split, [bs][1024]
__device__ bf16 g_Qsl[MTOT * DM];
__device__ bf16 g_Ksh[MTOT * DM];          // K proj split, [bs][1024]
__device__ bf16 g_Ksl[MTOT * DM];
__device__ bf16 g_Vthi[BATCH * NH * 64 * SEQ];   // V^T per head: [bh][d][key]
__device__ bf16 g_Vtlo[BATCH * NH * 64 * SEQ];

// ---------------------------------------------------------------------------
// Portable-PTX helpers (base sm_103 target: mma.sync / ldmatrix / cp.async)
// ---------------------------------------------------------------------------
__device__ __forceinline__ uint32_t cvta_smem(const void* p) {
    uint32_t a;
    asm("{ .reg .u64 t; cvta.to.shared.u64 t, %1; cvt.u32.u64 %0, t; }"
        : "=r"(a) : "l"(p));
    return a;
}
__device__ __forceinline__ void cp16(uint32_t saddr, const void* gaddr) {
    asm volatile("cp.async.cg.shared.global [%0], [%1], 16;"
                 :: "r"(saddr), "l"(gaddr));
}
__device__ __forceinline__ void cp_commit() {
    asm volatile("cp.async.commit_group;");
}
__device__ __forceinline__ void ldm4(uint32_t* r, uint32_t addr) {
    asm volatile("ldmatrix.sync.aligned.m8n8.x4.shared.b16 {%0,%1,%2,%3}, [%4];"
                 : "=r"(r[0]), "=r"(r[1]), "=r"(r[2]), "=r"(r[3]) : "r"(addr));
}
__device__ __forceinline__ void mma_bf16(float* c, const uint32_t* a, const uint32_t* b) {
    asm volatile(
        "mma.sync.aligned.m16n8k16.row.col.f32.bf16.bf16.f32 "
        "{%0,%1,%2,%3}, {%4,%5,%6,%7}, {%8,%9}, {%0,%1,%2,%3};"
        : "+f"(c[0]), "+f"(c[1]), "+f"(c[2]), "+f"(c[3])
        : "r"(a[0]), "r"(a[1]), "r"(a[2]), "r"(a[3]), "r"(b[0]), "r"(b[1]));
}
__device__ __forceinline__ uint32_t pack_bf16(float a, float b) {
    __nv_bfloat162 t;
    t.x = __float2bfloat16(a);
    t.y = __float2bfloat16(b);
    return *(uint32_t*)&t;
}

// ---------------------------------------------------------------------------
// Conversion kernels
// ---------------------------------------------------------------------------
__global__ void conv_x_kernel(const float* __restrict__ X)
{
    int i = (blockIdx.x * 256 + threadIdx.x) * 4;
    float4 v = *(const float4*)(X + i);
    bf16 h0 = __float2bfloat16(v.x), h1 = __float2bfloat16(v.y);
    bf16 h2 = __float2bfloat16(v.z), h3 = __float2bfloat16(v.w);
    bf16 l0 = __float2bfloat16(v.x - __bfloat162float(h0));
    bf16 l1 = __float2bfloat16(v.y - __bfloat162float(h1));
    bf16 l2 = __float2bfloat16(v.z - __bfloat162float(h2));
    bf16 l3 = __float2bfloat16(v.w - __bfloat162float(h3));
    __nv_bfloat162 hh0; hh0.x = h0; hh0.y = h1;
    __nv_bfloat162 hh1; hh1.x = h2; hh1.y = h3;
    __nv_bfloat162 ll0; ll0.x = l0; ll0.y = l1;
    __nv_bfloat162 ll1; ll1.x = l2; ll1.y = l3;
    *(__nv_bfloat162*)(g_Xhi + i)     = hh0;
    *(__nv_bfloat162*)(g_Xhi + i + 2) = hh1;
    *(__nv_bfloat162*)(g_Xlo + i)     = ll0;
    *(__nv_bfloat162*)(g_Xlo + i + 2) = ll1;
}

// Transpose + convert weights: W[k][n] fp32 -> WT[n][k] bf16 hi/lo.
__global__ void conv_w_kernel(const float* __restrict__ Wq, const float* __restrict__ Wk,
                              const float* __restrict__ Wv, const float* __restrict__ Wo)
{
    __shared__ float t[32][33];
    int z = blockIdx.z;
    const float* W = (z == 0) ? Wq : (z == 1) ? Wk : (z == 2) ? Wv : Wo;
    bf16* Th = g_WThi + (size_t)z * DM * DM;
    bf16* Tl = g_WTlo + (size_t)z * DM * DM;
    int k0 = blockIdx.y * 32, n0 = blockIdx.x * 32;
    int tx = threadIdx.x & 31, ty = threadIdx.x >> 5;  // 32 x 8
#pragma unroll
    for (int i = 0; i < 4; i++)
        t[ty + 8 * i][tx] = W[(size_t)(k0 + ty + 8 * i) * DM + n0 + tx];
    __syncthreads();
#pragma unroll
    for (int i = 0; i < 4; i++) {
        float x = t[tx][ty + 8 * i];
        bf16 h = __float2bfloat16(x);
        size_t o = (size_t)(n0 + ty + 8 * i) * DM + k0 + tx;
        Th[o] = h;
        Tl[o] = __float2bfloat16(x - __bfloat162float(h));
    }
}

// Transpose + split V per head: g_Vb[bs][1024] -> g_Vt*[bh][d][key]
__global__ void conv_vt_kernel()
{
    __shared__ float t[32][33];
    int s0 = blockIdx.x * 32;          // key tile
    int d0 = blockIdx.y * 32;          // d tile (0 or 32)
    int bh = blockIdx.z;
    int b  = bh >> 4, h = bh & 15;
    int tx = threadIdx.x & 31, ty = threadIdx.x >> 5;  // 32 x 8
#pragma unroll
    for (int i = 0; i < 4; i++)
        t[ty + 8 * i][tx] = g_Vb[(size_t)(b * SEQ + s0 + ty + 8 * i) * DM + h * 64 + d0 + tx];
    __syncthreads();
#pragma unroll
    for (int i = 0; i < 4; i++) {
        float x = t[tx][ty + 8 * i];   // V[key=s0+tx][d=d0+ty+8i]
        bf16 hh = __float2bfloat16(x);
        size_t o = (size_t)bh * 64 * SEQ + (size_t)(d0 + ty + 8 * i) * SEQ + s0 + tx;
        g_Vthi[o] = hh;
        g_Vtlo[o] = __float2bfloat16(x - __bfloat162float(hh));
    }
}

// ---------------------------------------------------------------------------
// HMMA split-bf16 GEMM, 128 threads (4 warps, 2m x 2n), CTA tile 128x128.
// Each warp computes 64x64 -> b-frags amortized over 4 m-tiles, halved
// operand traffic per flop vs 128x64; still 2 CTAs/SM (80KB smem, ~220 regs).
// 2-buffer single-sync pipeline.
// Output modes: Cf != nullptr -> fp32 (+bias); else split-bf16 (Chh, Cll).
// ---------------------------------------------------------------------------
#define BK          32
#define ASTRIDE     40
#define OA_HI       0
#define OA_LO       10240                  // 128 rows * 40 * 2B
#define OB_HI       20480
#define OB_LO       30720                  // B also 128 rows now
#define STAGE_BYTES 40960
#define DYN_SMEM    (2 * STAGE_BYTES)      // 81920 B

__device__ __forceinline__ void g_load_stage(
    uint32_t sbase, int buf,
    const bf16* __restrict__ Ah, const bf16* __restrict__ Al,
    const bf16* __restrict__ Bh, const bf16* __restrict__ Bl,
    int m0, int n0, int k0, int tid)
{
    uint32_t sb = sbase + buf * STAGE_BYTES;
#pragma unroll
    for (int e = 0; e < 4; e++) {
        int lin = tid + 128 * e;             // 0..511
        int row = lin >> 2;                  // 0..127
        int ch  = lin & 3;
        uint32_t soff = (uint32_t)(row * ASTRIDE + ch * 8) * 2;
        size_t gA = (size_t)(m0 + row) * DM + k0 + ch * 8;
        size_t gB = (size_t)(n0 + row) * DM + k0 + ch * 8;
        cp16(sb + OA_HI + soff, Ah + gA);
        cp16(sb + OA_LO + soff, Al + gA);
        cp16(sb + OB_HI + soff, Bh + gB);
        cp16(sb + OB_LO + soff, Bl + gB);
    }
    cp_commit();
}

__device__ __forceinline__ void g_compute_stage(
    uint32_t sbase, int buf, float (*acc)[8][4], int wm, int wn, int lane)
{
    uint32_t sb = sbase + buf * STAGE_BYTES;
#pragma unroll
    for (int ks = 0; ks < 2; ks++) {
        uint32_t ah[4][4], al[4][4];
#pragma unroll
        for (int mt = 0; mt < 4; mt++) {
            int row = wm * 64 + mt * 16 + (lane & 15);
            int ch  = ks * 2 + (lane >> 4);
            uint32_t ad = sb + OA_HI + (uint32_t)(row * ASTRIDE + ch * 8) * 2;
            ldm4(ah[mt], ad);
            ldm4(al[mt], ad + (OA_LO - OA_HI));
        }
        uint32_t bh[8][2], bl[8][2];
#pragma unroll
        for (int p = 0; p < 4; p++) {
            int row = wn * 64 + p * 16 + ((lane >> 4) << 3) + (lane & 7);
            int ch  = ks * 2 + ((lane >> 3) & 1);
            uint32_t bd = sb + OB_HI + (uint32_t)(row * ASTRIDE + ch * 8) * 2;
            uint32_t r[4];
            ldm4(r, bd);
            bh[2 * p][0] = r[0]; bh[2 * p][1] = r[1];
            bh[2 * p + 1][0] = r[2]; bh[2 * p + 1][1] = r[3];
            ldm4(r, bd + (OB_LO - OB_HI));
            bl[2 * p][0] = r[0]; bl[2 * p][1] = r[1];
            bl[2 * p + 1][0] = r[2]; bl[2 * p + 1][1] = r[3];
        }
#pragma unroll
        for (int mt = 0; mt < 4; mt++)
#pragma unroll
            for (int nt = 0; nt < 8; nt++) {
                mma_bf16(acc[mt][nt], ah[mt], bh[nt]);
                mma_bf16(acc[mt][nt], ah[mt], bl[nt]);
                mma_bf16(acc[mt][nt], al[mt], bh[nt]);
            }
    }
}

__device__ __forceinline__ void gemm128_body(
    const bf16* __restrict__ Ah, const bf16* __restrict__ Al,
    const bf16* __restrict__ Bh, const bf16* __restrict__ Bl,
    float* __restrict__ Cf, bf16* __restrict__ Chh, bf16* __restrict__ Cll,
    const float* __restrict__ bias, float scale, int m0, int n0)
{
    extern __shared__ bf16 smem[];
    const int tid  = threadIdx.x;
    const int lane = tid & 31;
    const int wid  = tid >> 5;       // 0..3
    const int wm   = wid & 1;        // m half (64 rows)
    const int wn   = wid >> 1;       // n half (64 cols)
    uint32_t sbase = cvta_smem(smem);

    float acc[4][8][4];
#pragma unroll
    for (int i = 0; i < 4; i++)
#pragma unroll
        for (int j = 0; j < 8; j++)
#pragma unroll
            for (int k = 0; k < 4; k++) acc[i][j][k] = 0.f;

    g_load_stage(sbase, 0, Ah, Al, Bh, Bl, m0, n0, 0, tid);

    const int NST = DM / BK;   // 32
    for (int s = 0; s < NST; s++) {
        asm volatile("cp.async.wait_group 0;");   // load s complete
        __syncthreads();                          // visible to all; buf s+1 free
        if (s + 1 < NST)
            g_load_stage(sbase, (s + 1) & 1, Ah, Al, Bh, Bl, m0, n0, (s + 1) * BK, tid);
        g_compute_stage(sbase, s & 1, acc, wm, wn, lane);
    }

#pragma unroll
    for (int mt = 0; mt < 4; mt++) {
#pragma unroll
        for (int nt = 0; nt < 8; nt++) {
            int r = m0 + wm * 64 + mt * 16 + (lane >> 2);
            int c = n0 + wn * 64 + nt * 8 + (lane & 3) * 2;
            float x0 = acc[mt][nt][0] * scale, y0 = acc[mt][nt][1] * scale;
            float x1 = acc[mt][nt][2] * scale, y1 = acc[mt][nt][3] * scale;
            if (Cf) {
                if (bias) { x0 += bias[c]; y0 += bias[c + 1]; x1 += bias[c]; y1 += bias[c + 1]; }
                float2 v0; v0.x = x0; v0.y = y0;
                float2 v1; v1.x = x1; v1.y = y1;
                *(float2*)(Cf + (size_t)r * DM + c)       = v0;
                *(float2*)(Cf + (size_t)(r + 8) * DM + c) = v1;
            } else {
                bf16 hx0 = __float2bfloat16(x0), hy0 = __float2bfloat16(y0);
                bf16 hx1 = __float2bfloat16(x1), hy1 = __float2bfloat16(y1);
                __nv_bfloat162 h0; h0.x = hx0; h0.y = hy0;
                __nv_bfloat162 h1; h1.x = hx1; h1.y = hy1;
                __nv_bfloat162 l0; l0.x = __float2bfloat16(x0 - __bfloat162float(hx0));
                l0.y = __float2bfloat16(y0 - __bfloat162float(hy0));
                __nv_bfloat162 l1; l1.x = __float2bfloat16(x1 - __bfloat162float(hx1));
                l1.y = __float2bfloat16(y1 - __bfloat162float(hy1));
                *(__nv_bfloat162*)(Chh + (size_t)r * DM + c)       = h0;
                *(__nv_bfloat162*)(Chh + (size_t)(r + 8) * DM + c) = h1;
                *(__nv_bfloat162*)(Cll + (size_t)r * DM + c)       = l0;
                *(__nv_bfloat162*)(Cll + (size_t)(r + 8) * DM + c) = l1;
            }
        }
    }
}

__global__ __launch_bounds__(128)
void proj_mm_kernel()
{
    int z = blockIdx.z;
    const bf16* Bh = g_WThi + (size_t)z * DM * DM;
    const bf16* Bl = g_WTlo + (size_t)z * DM * DM;
    int m0 = blockIdx.y * 128, n0 = blockIdx.x * 128;
    if (z == 0)
        gemm128_body(g_Xhi, g_Xlo, Bh, Bl, nullptr, g_Qsh, g_Qsl, nullptr, 0.125f, m0, n0);
    else if (z == 1)
        gemm128_body(g_Xhi, g_Xlo, Bh, Bl, nullptr, g_Ksh, g_Ksl, nullptr, 1.0f, m0, n0);
    else
        gemm128_body(g_Xhi, g_Xlo, Bh, Bl, g_Vb, nullptr, nullptr, nullptr, 1.0f, m0, n0);
}

__global__ __launch_bounds__(128)
void out_mm_kernel(const float* __restrict__ bo, float* __restrict__ Y)
{
    gemm128_body(g_Chi, g_Clo,
                 g_WThi + (size_t)3 * DM * DM, g_WTlo + (size_t)3 * DM * DM,
                 Y, nullptr, nullptr, bo, 1.0f, blockIdx.y * 128, blockIdx.x * 128);
}

// ---------------------------------------------------------------------------
// FlashAttention-2 on mma.sync, split-bf16, 2-buffer single-sync K/V pipeline.
// 128 threads (4 warps x 16 q-rows = 64-query tile) -> 2 CTAs/SM so the
// softmax phase of one CTA overlaps the MMA phase of the other. (R14 config.)
// ---------------------------------------------------------------------------
#define ATP   72
#define ABUF_BYTES (4 * 64 * ATP * 2)      // K hi/lo + V hi/lo = 36864 B
#define AKH   0
#define AKL   4608
#define AVH   9216
#define AVL   13824
#define AQLO  4608                          // Q lo element offset (64 rows)
#define ATT_SMEM (2 * ABUF_BYTES)          // 73728 B

__device__ __forceinline__ void attn_load_kv(
    uint32_t sb, int buf, size_t kbase, size_t vbase, int kt, int tid)
{
    uint32_t sbb = sb + buf * ABUF_BYTES;
#pragma unroll
    for (int e = 0; e < 4; e++) {
        int lin = tid + 128 * e;       // 0..511
        int row = lin >> 3;            // 0..63
        int ch  = lin & 7;
        size_t gk = kbase + (size_t)(kt * 64 + row) * DM + ch * 8;
        size_t gv = vbase + (size_t)row * SEQ + kt * 64 + ch * 8;
        cp16(sbb + (uint32_t)(AKH + row * ATP + ch * 8) * 2, g_Ksh + gk);
        cp16(sbb + (uint32_t)(AKL + row * ATP + ch * 8) * 2, g_Ksl + gk);
        cp16(sbb + (uint32_t)(AVH + row * ATP + ch * 8) * 2, g_Vthi + gv);
        cp16(sbb + (uint32_t)(AVL + row * ATP + ch * 8) * 2, g_Vtlo + gv);
    }
    cp_commit();
}

__global__ __launch_bounds__(128)
void attn_mm_kernel()
{
    extern __shared__ bf16 asmem[];
    const int tid  = threadIdx.x;
    const int lane = tid & 31;
    const int w    = tid >> 5;         // 0..3
    const int bh   = blockIdx.x;
    const int b    = bh >> 4, h = bh & 15;
    const int q0   = blockIdx.y * 64;
    uint32_t sb = cvta_smem(asmem);

    // --- Stage Q tile (64 x 64, hi/lo) in buffer 0 region; load a-frags ---
#pragma unroll
    for (int e = 0; e < 4; e++) {
        int lin = tid + 128 * e;           // 0..511
        int row = lin >> 3;                // 0..63
        int ch  = lin & 7;
        size_t g = (size_t)(b * SEQ + q0 + row) * DM + h * 64 + ch * 8;
        cp16(sb + (uint32_t)(row * ATP + ch * 8) * 2,          g_Qsh + g);
        cp16(sb + (uint32_t)(AQLO + row * ATP + ch * 8) * 2,   g_Qsl + g);
    }
    cp_commit();
    asm volatile("cp.async.wait_group 0;");
    __syncthreads();

    uint32_t qh[4][4], ql[4][4];
#pragma unroll
    for (int ks = 0; ks < 4; ks++) {
        int row = w * 16 + (lane & 15);
        int ch  = ks * 2 + (lane >> 4);
        uint32_t ad = sb + (uint32_t)(row * ATP + ch * 8) * 2;
        ldm4(qh[ks], ad);
        ldm4(ql[ks], ad + AQLO * 2);
    }
    __syncthreads();   // Q consumed; smem becomes K/V double buffer

    float o[8][4];
#pragma unroll
    for (int nt = 0; nt < 8; nt++)
#pragma unroll
        for (int k = 0; k < 4; k++) o[nt][k] = 0.f;
    float m0 = -1e30f, m1 = -1e30f, l0 = 0.f, l1 = 0.f;

    const size_t kbase = (size_t)(b * SEQ) * DM + h * 64;
    const size_t vbase = (size_t)bh * 64 * SEQ;
    const int NKT = SEQ / 64;

    attn_load_kv(sb, 0, kbase, vbase, 0, tid);

    for (int kt = 0; kt < NKT; kt++) {
        asm volatile("cp.async.wait_group 0;");   // load kt complete
        __syncthreads();                          // visible; buf kt+1 free
        if (kt + 1 < NKT)
            attn_load_kv(sb, (kt + 1) & 1, kbase, vbase, kt + 1, tid);
        uint32_t sbb = sb + (kt & 1) * ABUF_BYTES;

        // --- S = Q K^T ---
        float s[8][4];
#pragma unroll
        for (int nt = 0; nt < 8; nt++)
#pragma unroll
            for (int k = 0; k < 4; k++) s[nt][k] = 0.f;

#pragma unroll
        for (int ks = 0; ks < 4; ks++) {
            uint32_t kbh[8][2], kbl[8][2];
#pragma unroll
            for (int p = 0; p < 4; p++) {
                int row = p * 16 + ((lane >> 4) << 3) + (lane & 7);
                int ch  = ks * 2 + ((lane >> 3) & 1);
                uint32_t ad = sbb + (uint32_t)(AKH + row * ATP + ch * 8) * 2;
                uint32_t r[4];
                ldm4(r, ad);
                kbh[2 * p][0] = r[0]; kbh[2 * p][1] = r[1];
                kbh[2 * p + 1][0] = r[2]; kbh[2 * p + 1][1] = r[3];
                ldm4(r, ad + (AKL - AKH) * 2);
                kbl[2 * p][0] = r[0]; kbl[2 * p][1] = r[1];
                kbl[2 * p + 1][0] = r[2]; kbl[2 * p + 1][1] = r[3];
            }
#pragma unroll
            for (int nt = 0; nt < 8; nt++) {
                mma_bf16(s[nt], qh[ks], kbh[nt]);
                mma_bf16(s[nt], qh[ks], kbl[nt]);
                mma_bf16(s[nt], ql[ks], kbh[nt]);
            }
        }

        // --- online softmax (rows r0 = lane>>2, r1 = r0+8) ---
        float mx0 = -1e30f, mx1 = -1e30f;
#pragma unroll
        for (int nt = 0; nt < 8; nt++) {
            mx0 = fmaxf(mx0, fmaxf(s[nt][0], s[nt][1]));
            mx1 = fmaxf(mx1, fmaxf(s[nt][2], s[nt][3]));
        }
        mx0 = fmaxf(mx0, __shfl_xor_sync(0xffffffffu, mx0, 1));
        mx0 = fmaxf(mx0, __shfl_xor_sync(0xffffffffu, mx0, 2));
        mx1 = fmaxf(mx1, __shfl_xor_sync(0xffffffffu, mx1, 1));
        mx1 = fmaxf(mx1, __shfl_xor_sync(0xffffffffu, mx1, 2));
        float nm0 = fmaxf(m0, mx0), nm1 = fmaxf(m1, mx1);
        float c0 = __expf(m0 - nm0), c1 = __expf(m1 - nm1);
        m0 = nm0; m1 = nm1;
        float rs0 = 0.f, rs1 = 0.f;
#pragma unroll
        for (int nt = 0; nt < 8; nt++) {
            s[nt][0] = __expf(s[nt][0] - nm0);
            s[nt][1] = __expf(s[nt][1] - nm0);
            s[nt][2] = __expf(s[nt][2] - nm1);
            s[nt][3] = __expf(s[nt][3] - nm1);
            rs0 += s[nt][0] + s[nt][1];
            rs1 += s[nt][2] + s[nt][3];
        }
        rs0 += __shfl_xor_sync(0xffffffffu, rs0, 1);
        rs0 += __shfl_xor_sync(0xffffffffu, rs0, 2);
        rs1 += __shfl_xor_sync(0xffffffffu, rs1, 1);
        rs1 += __shfl_xor_sync(0xffffffffu, rs1, 2);
        l0 = l0 * c0 + rs0;
        l1 = l1 * c1 + rs1;
#pragma unroll
        for (int nt = 0; nt < 8; nt++) {
            o[nt][0] *= c0; o[nt][1] *= c0;
            o[nt][2] *= c1; o[nt][3] *= c1;
        }

        // --- P -> split-bf16 a-frags (register repack; no smem) ---
        uint32_t pha[4][4], pla[4][4];
#pragma unroll
        for (int g = 0; g < 4; g++) {
            int t0 = 2 * g, t1 = 2 * g + 1;
            pha[g][0] = pack_bf16(s[t0][0], s[t0][1]);
            pha[g][1] = pack_bf16(s[t0][2], s[t0][3]);
            pha[g][2] = pack_bf16(s[t1][0], s[t1][1]);
            pha[g][3] = pack_bf16(s[t1][2], s[t1][3]);
            float r00 = s[t0][0] - __bfloat162float(__float2bfloat16(s[t0][0]));
            float r01 = s[t0][1] - __bfloat162float(__float2bfloat16(s[t0][1]));
            float r02 = s[t0][2] - __bfloat162float(__float2bfloat16(s[t0][2]));
            float r03 = s[t0][3] - __bfloat162float(__float2bfloat16(s[t0][3]));
            float r10 = s[t1][0] - __bfloat162float(__float2bfloat16(s[t1][0]));
            float r11 = s[t1][1] - __bfloat162float(__float2bfloat16(s[t1][1]));
            float r12 = s[t1][2] - __bfloat162float(__float2bfloat16(s[t1][2]));
            float r13 = s[t1][3] - __bfloat162float(__float2bfloat16(s[t1][3]));
            pla[g][0] = pack_bf16(r00, r01);
            pla[g][1] = pack_bf16(r02, r03);
            pla[g][2] = pack_bf16(r10, r11);
            pla[g][3] = pack_bf16(r12, r13);
        }

        // --- O += P V ---
#pragma unroll
        for (int ks = 0; ks < 4; ks++) {
            uint32_t vbh[8][2], vbl[8][2];
#pragma unroll
            for (int p = 0; p < 4; p++) {
                int row = p * 16 + ((lane >> 4) << 3) + (lane & 7);
                int ch  = ks * 2 + ((lane >> 3) & 1);
                uint32_t ad = sbb + (uint32_t)(AVH + row * ATP + ch * 8) * 2;
                uint32_t r[4];
                ldm4(r, ad);
                vbh[2 * p][0] = r[0]; vbh[2 * p][1] = r[1];
                vbh[2 * p + 1][0] = r[2]; vbh[2 * p + 1][1] = r[3];
                ldm4(r, ad + (AVL - AVH) * 2);
                vbl[2 * p][0] = r[0]; vbl[2 * p][1] = r[1];
                vbl[2 * p + 1][0] = r[2]; vbl[2 * p + 1][1] = r[3];
            }
#pragma unroll
            for (int nt = 0; nt < 8; nt++) {
                mma_bf16(o[nt], pha[ks], vbh[nt]);
                mma_bf16(o[nt], pha[ks], vbl[nt]);
                mma_bf16(o[nt], pla[ks], vbh[nt]);
            }
        }
    }

    // --- normalize, split-convert, write ctx hi/lo directly ---
    float inv0 = 1.0f / l0, inv1 = 1.0f / l1;
    int r0 = q0 + w * 16 + (lane >> 2);
#pragma unroll
    for (int nt = 0; nt < 8; nt++) {
        int c = h * 64 + nt * 8 + (lane & 3) * 2;
        float x0 = o[nt][0] * inv0, y0 = o[nt][1] * inv0;
        float x1 = o[nt][2] * inv1, y1 = o[nt][3] * inv1;
        bf16 hx0 = __float2bfloat16(x0), hy0 = __float2bfloat16(y0);
        bf16 hx1 = __float2bfloat16(x1), hy1 = __float2bfloat16(y1);
        __nv_bfloat162 h0; h0.x = hx0; h0.y = hy0;
        __nv_bfloat162 h1; h1.x = hx1; h1.y = hy1;
        __nv_bfloat162 lo0; lo0.x = __float2bfloat16(x0 - __bfloat162float(hx0));
        lo0.y = __float2bfloat16(y0 - __bfloat162float(hy0));
        __nv_bfloat162 lo1; lo1.x = __float2bfloat16(x1 - __bfloat162float(hx1));
        lo1.y = __float2bfloat16(y1 - __bfloat162float(hy1));
        size_t base0 = (size_t)(b * SEQ + r0) * DM + c;
        size_t base1 = (size_t)(b * SEQ + r0 + 8) * DM + c;
        *(__nv_bfloat162*)(g_Chi + base0) = h0;
        *(__nv_bfloat162*)(g_Chi + base1) = h1;
        *(__nv_bfloat162*)(g_Clo + base0) = lo0;
        *(__nv_bfloat162*)(g_Clo + base1) = lo1;
    }
}

// ---------------------------------------------------------------------------
extern "C" void kernel_launch(void* const* d_in, const int* in_sizes, int n_in,
                              void* d_out, int out_size)
{
    const float* q  = (const float*)d_in[0];
    const float* Wq = (const float*)d_in[1];
    const float* Wk = (const float*)d_in[2];
    const float* Wv = (const float*)d_in[3];
    const float* Wo = (const float*)d_in[4];
    const float* bo = (const float*)d_in[5];

    cudaFuncSetAttribute(proj_mm_kernel, cudaFuncAttributeMaxDynamicSharedMemorySize, DYN_SMEM);
    cudaFuncSetAttribute(out_mm_kernel,  cudaFuncAttributeMaxDynamicSharedMemorySize, DYN_SMEM);
    cudaFuncSetAttribute(attn_mm_kernel, cudaFuncAttributeMaxDynamicSharedMemorySize, ATT_SMEM);

    // 1. split-bf16 conversion of input and (transposed) weights
    conv_x_kernel<<<MTOT * DM / 1024, 256>>>(q);
    conv_w_kernel<<<dim3(32, 32, 4), 256>>>(Wq, Wk, Wv, Wo);

    // 2. Q/K/V projections (Q pre-scaled; Q,K emitted split-bf16, V fp32)
    proj_mm_kernel<<<dim3(8, 32, 3), 128, DYN_SMEM>>>();

    // 3. V transpose + split per head
    conv_vt_kernel<<<dim3(SEQ / 32, 2, BATCH * NH), 256>>>();

    // 4. flash attention (64-query CTAs; 2 CTAs/SM phase overlap)
    attn_mm_kernel<<<dim3(BATCH * NH, SEQ / 64), 128, ATT_SMEM>>>();

    // 5. output projection (+bias)
    out_mm_kernel<<<dim3(8, 32), 128, DYN_SMEM>>>(bo, (float*)d_out);
}